// round 11
// baseline (speedup 1.0000x reference)
#include <cuda_runtime.h>
#include <cuda_fp16.h>
#include <math.h>
#include <stdint.h>

#define D_MODEL 1024
#define NHEADS  16
#define HDIM    64
#define BATCH   2
#define SEQ     2048
#define MROWS   (BATCH*SEQ)   // 4096
#define PLN     (MROWS*D_MODEL)

// ---------------- device scratch ----------------
__device__ __align__(128) float g_sums[4];
__device__ __align__(128) int   g_amaxb[2];                 // 0: value, 1: O
__device__ __align__(128) __half g_Wh[2][D_MODEL*D_MODEL];  // wq, wk (fp16)
__device__ __align__(128) char   g_W8[2][D_MODEL*D_MODEL];  // wv, wo (int8)
__device__ __align__(128) __half g_Xh[2][PLN];  // q,k input hi planes
__device__ __align__(128) __half g_Xl[2][PLN];  // q,k input lo planes
__device__ __align__(128) char  g_V8a[PLN], g_V8b[PLN];     // value int8 planes
__device__ __align__(128) char  g_O8a[PLN], g_O8b[PLN];     // O int8 planes
__device__ __align__(128) __half g_Qh[PLN];     // Q hi (pre-scaled 0.125*log2e)
__device__ __align__(128) __half g_Ql[PLN];
__device__ __align__(128) __half g_Kh[PLN];
__device__ __align__(128) __half g_Kl[PLN];
__device__ __align__(128) __half g_Vh[PLN];
__device__ __align__(128) __half g_Oh[PLN];
__device__ __align__(128) __half g_Ol[PLN];

#define QSCALE 0.18033688011112042f   // 0.125 * log2(e)

// ---------------- helpers ----------------
__device__ __forceinline__ void mma_f16(float* c,
    uint32_t a0, uint32_t a1, uint32_t a2, uint32_t a3,
    uint32_t b0, uint32_t b1)
{
    asm volatile(
        "mma.sync.aligned.m16n8k16.row.col.f32.f16.f16.f32 "
        "{%0,%1,%2,%3}, {%4,%5,%6,%7}, {%8,%9}, {%0,%1,%2,%3};"
        : "+f"(c[0]), "+f"(c[1]), "+f"(c[2]), "+f"(c[3])
        : "r"(a0), "r"(a1), "r"(a2), "r"(a3), "r"(b0), "r"(b1));
}

__device__ __forceinline__ void mma_s8(int* c,
    uint32_t a0, uint32_t a1, uint32_t a2, uint32_t a3,
    uint32_t b0, uint32_t b1)
{
    asm volatile(
        "mma.sync.aligned.m16n8k32.row.col.s32.s8.s8.s32 "
        "{%0,%1,%2,%3}, {%4,%5,%6,%7}, {%8,%9}, {%0,%1,%2,%3};"
        : "+r"(c[0]), "+r"(c[1]), "+r"(c[2]), "+r"(c[3])
        : "r"(a0), "r"(a1), "r"(a2), "r"(a3), "r"(b0), "r"(b1));
}

__device__ __forceinline__ void split2x(float x, float y, uint32_t& hp, uint32_t& lp) {
    __half hx = __float2half_rn(x);
    __half hy = __float2half_rn(y);
    __half lx = __float2half_rn(x - __half2float(hx));
    __half ly = __float2half_rn(y - __half2float(hy));
    __half2 h2 = __halves2half2(hx, hy);
    __half2 l2 = __halves2half2(lx, ly);
    hp = *reinterpret_cast<uint32_t*>(&h2);
    lp = *reinterpret_cast<uint32_t*>(&l2);
}
__device__ __forceinline__ uint32_t pack_h2(float x, float y) {
    __half2 t = __floats2half2_rn(x, y);
    return *reinterpret_cast<uint32_t*>(&t);
}

// ---------------- ternarize ----------------
__global__ void zero_sums_kernel() {
    if (threadIdx.x < 4) g_sums[threadIdx.x] = 0.0f;
    if (threadIdx.x < 2) g_amaxb[threadIdx.x] = 0;
}

__global__ __launch_bounds__(256) void abssum_kernel(
    const float* __restrict__ w0, const float* __restrict__ w1,
    const float* __restrict__ w2, const float* __restrict__ w3)
{
    const float* w = (blockIdx.y == 0) ? w0 : (blockIdx.y == 1) ? w1
                     : (blockIdx.y == 2) ? w2 : w3;
    const int n = D_MODEL * D_MODEL;
    float s = 0.0f;
    for (int i = blockIdx.x * blockDim.x + threadIdx.x; i < n;
         i += gridDim.x * blockDim.x)
        s += fabsf(w[i]);
    __shared__ float red[256];
    red[threadIdx.x] = s;
    __syncthreads();
    for (int o = 128; o > 0; o >>= 1) {
        if (threadIdx.x < o) red[threadIdx.x] += red[threadIdx.x + o];
        __syncthreads();
    }
    if (threadIdx.x == 0) atomicAdd(&g_sums[blockIdx.y], red[0]);
}

__global__ __launch_bounds__(256) void ternarize_kernel(
    const float* __restrict__ w0, const float* __restrict__ w1,
    const float* __restrict__ w2, const float* __restrict__ w3)
{
    const int m = blockIdx.y;
    const float* w = (m == 0) ? w0 : (m == 1) ? w1 : (m == 2) ? w2 : w3;
    const float mean = g_sums[m] * (1.0f / (float)(D_MODEL * D_MODEL));
    int i = blockIdx.x * blockDim.x + threadIdx.x;
    float v = w[i];
    float t = (fabsf(v) > mean) ? (v > 0.0f ? 1.0f : -1.0f) : 0.0f;
    if (m < 2) g_Wh[m][i] = __float2half_rn(t);
    else       g_W8[m - 2][i] = (char)(int)t;
}

// ---------------- pre-split q,k inputs into fp16 h/l planes ----------------
__global__ __launch_bounds__(256) void presplit_kernel(
    const float* __restrict__ q, const float* __restrict__ k)
{
    const int z = blockIdx.y;
    const float* src = (z == 0) ? q : k;
    __half* hP = g_Xh[z];
    __half* lP = g_Xl[z];
    const int i = (blockIdx.x * blockDim.x + threadIdx.x) * 4;
    float4 val = *(const float4*)(src + i);
    uint32_t h0, l0, h1, l1;
    split2x(val.x, val.y, h0, l0);
    split2x(val.z, val.w, h1, l1);
    *(uint32_t*)(hP + i)     = h0;
    *(uint32_t*)(hP + i + 2) = h1;
    *(uint32_t*)(lP + i)     = l0;
    *(uint32_t*)(lP + i + 2) = l1;
}

// ---------------- absmax + quantize (fp32 source) ----------------
__global__ __launch_bounds__(256) void amax_f32_kernel(const float* __restrict__ src, int idx)
{
    const int i = (blockIdx.x * 256 + threadIdx.x) * 4;
    float4 v = *(const float4*)(src + i);
    float m = fmaxf(fmaxf(fabsf(v.x), fabsf(v.y)), fmaxf(fabsf(v.z), fabsf(v.w)));
    __shared__ float red[256];
    red[threadIdx.x] = m;
    __syncthreads();
    for (int o = 128; o > 0; o >>= 1) {
        if (threadIdx.x < o) red[threadIdx.x] = fmaxf(red[threadIdx.x], red[threadIdx.x + o]);
        __syncthreads();
    }
    if (threadIdx.x == 0) atomicMax(&g_amaxb[idx], __float_as_int(red[0]));
}

__device__ __forceinline__ void quant4(float4 v, float inv1, float s1, float inv2,
                                       uint32_t& p1, uint32_t& p2)
{
    p1 = 0; p2 = 0;
    float vv[4] = { v.x, v.y, v.z, v.w };
#pragma unroll
    for (int j = 0; j < 4; j++) {
        int q  = (int)rintf(vv[j] * inv1);
        float r = vv[j] - (float)q * s1;
        int q2 = (int)rintf(r * inv2);
        p1 |= (uint32_t)(q  & 255) << (8 * j);
        p2 |= (uint32_t)(q2 & 255) << (8 * j);
    }
}

__global__ __launch_bounds__(256) void quant_f32_kernel(
    const float* __restrict__ src, char* __restrict__ q1, char* __restrict__ q2, int idx)
{
    const float amax = __int_as_float(g_amaxb[idx]);
    const float inv1 = 127.0f / amax;
    const float s1   = amax / 127.0f;
    const float inv2 = 192.0f / s1;
    const int i = (blockIdx.x * 256 + threadIdx.x) * 4;
    float4 v = *(const float4*)(src + i);
    uint32_t p1, p2;
    quant4(v, inv1, s1, inv2, p1, p2);
    *(uint32_t*)(q1 + i) = p1;
    *(uint32_t*)(q2 + i) = p2;
}

// ---------------- absmax + quantize for O (from fp16 h/l planes) ----------------
__global__ __launch_bounds__(256) void amax_O_kernel()
{
    const int i = (blockIdx.x * 256 + threadIdx.x) * 4;
    float m = 0.0f;
#pragma unroll
    for (int j = 0; j < 4; j++) {
        float o = __half2float(g_Oh[i + j]) + __half2float(g_Ol[i + j]);
        m = fmaxf(m, fabsf(o));
    }
    __shared__ float red[256];
    red[threadIdx.x] = m;
    __syncthreads();
    for (int o = 128; o > 0; o >>= 1) {
        if (threadIdx.x < o) red[threadIdx.x] = fmaxf(red[threadIdx.x], red[threadIdx.x + o]);
        __syncthreads();
    }
    if (threadIdx.x == 0) atomicMax(&g_amaxb[1], __float_as_int(red[0]));
}

__global__ __launch_bounds__(256) void quant_O_kernel()
{
    const float amax = __int_as_float(g_amaxb[1]);
    const float inv1 = 127.0f / amax;
    const float s1   = amax / 127.0f;
    const float inv2 = 192.0f / s1;
    const int i = (blockIdx.x * 256 + threadIdx.x) * 4;
    float4 v;
    v.x = __half2float(g_Oh[i + 0]) + __half2float(g_Ol[i + 0]);
    v.y = __half2float(g_Oh[i + 1]) + __half2float(g_Ol[i + 1]);
    v.z = __half2float(g_Oh[i + 2]) + __half2float(g_Ol[i + 2]);
    v.w = __half2float(g_Oh[i + 3]) + __half2float(g_Ol[i + 3]);
    uint32_t p1, p2;
    quant4(v, inv1, s1, inv2, p1, p2);
    *(uint32_t*)(g_O8a + i) = p1;
    *(uint32_t*)(g_O8b + i) = p2;
}

// ---------------- fp16 GEMM (Q/K projections) ----------------
#define GBM 128
#define GBN 128
#define GBK 32
#define SRH 40
#define NCH (D_MODEL/GBK)
#define GPL (GBM*SRH*2)
#define GST (3*GPL)
#define GEMM_SMEM (2*GST)      // 61440

__global__ __launch_bounds__(256, 2) void gemm_h2_kernel()
{
    extern __shared__ char gsm[];

    const int tid  = threadIdx.x;
    const int lane = tid & 31;
    const int wid  = tid >> 5;
    const int wm   = wid & 1;
    const int wn   = wid >> 1;
    const int g    = lane >> 2;
    const int tig  = lane & 3;

    const int z  = blockIdx.z;          // 0: Q, 1: K
    const __half* Ah_ = g_Xh[z];
    const __half* Al_ = g_Xl[z];
    const __half* W_  = g_Wh[z];

    const int bm = blockIdx.y * GBM;
    const int bn = blockIdx.x * GBN;

    const int lr = tid >> 1;
    const int lk = (tid & 1) * 16;
    const __half* AhP = Ah_ + (size_t)(bm + lr) * D_MODEL + lk;
    const __half* AlP = Al_ + (size_t)(bm + lr) * D_MODEL + lk;
    const __half* WP  = W_  + (size_t)(bn + lr) * D_MODEL + lk;
    const int soff = lr * (SRH * 2) + lk * 2;

    float acc[4][4][4];
#pragma unroll
    for (int mf = 0; mf < 4; mf++)
#pragma unroll
        for (int nf = 0; nf < 4; nf++)
#pragma unroll
            for (int r = 0; r < 4; r++) acc[mf][nf][r] = 0.0f;

    uint4 pah0 = *(const uint4*)(AhP);
    uint4 pah1 = *(const uint4*)(AhP + 8);
    uint4 pal0 = *(const uint4*)(AlP);
    uint4 pal1 = *(const uint4*)(AlP + 8);
    uint4 pb0  = *(const uint4*)(WP);
    uint4 pb1  = *(const uint4*)(WP + 8);
    {
        uint4* dh = (uint4*)(gsm + 0 * GST + 0 * GPL + soff);
        uint4* dl = (uint4*)(gsm + 0 * GST + 1 * GPL + soff);
        uint4* db = (uint4*)(gsm + 0 * GST + 2 * GPL + soff);
        dh[0] = pah0; dh[1] = pah1;
        dl[0] = pal0; dl[1] = pal1;
        db[0] = pb0;  db[1] = pb1;
    }
    __syncthreads();

    for (int c = 0; c < NCH; c++) {
        const char* st = gsm + (c & 1) * GST;

        if (c + 1 < NCH) {
            const int ko = (c + 1) * GBK;
            pah0 = *(const uint4*)(AhP + ko);
            pah1 = *(const uint4*)(AhP + ko + 8);
            pal0 = *(const uint4*)(AlP + ko);
            pal1 = *(const uint4*)(AlP + ko + 8);
            pb0  = *(const uint4*)(WP + ko);
            pb1  = *(const uint4*)(WP + ko + 8);
        }

#pragma unroll
        for (int s = 0; s < 2; s++) {
            uint32_t bf[4][2];
#pragma unroll
            for (int nf = 0; nf < 4; nf++) {
                const int n = wn * 32 + nf * 8 + g;
                const uint32_t* bp = (const uint32_t*)(st + 2 * GPL + n * SRH * 2) + s * 8 + tig;
                bf[nf][0] = bp[0];
                bf[nf][1] = bp[4];
            }
#pragma unroll
            for (int mf = 0; mf < 4; mf++) {
                const int m = wm * 64 + mf * 16;
                const uint32_t* ah0p = (const uint32_t*)(st + 0 * GPL + (m + g) * SRH * 2) + s * 8 + tig;
                const uint32_t* ah1p = (const uint32_t*)(st + 0 * GPL + (m + g + 8) * SRH * 2) + s * 8 + tig;
                const uint32_t* al0p = (const uint32_t*)(st + 1 * GPL + (m + g) * SRH * 2) + s * 8 + tig;
                const uint32_t* al1p = (const uint32_t*)(st + 1 * GPL + (m + g + 8) * SRH * 2) + s * 8 + tig;
                uint32_t h0 = ah0p[0], h2 = ah0p[4];
                uint32_t h1 = ah1p[0], h3 = ah1p[4];
                uint32_t l0 = al0p[0], l2 = al0p[4];
                uint32_t l1 = al1p[0], l3 = al1p[4];
#pragma unroll
                for (int nf = 0; nf < 4; nf++) {
                    mma_f16(acc[mf][nf], l0, l1, l2, l3, bf[nf][0], bf[nf][1]);
                    mma_f16(acc[mf][nf], h0, h1, h2, h3, bf[nf][0], bf[nf][1]);
                }
            }
        }

        if (c + 1 < NCH) {
            char* nst = gsm + ((c + 1) & 1) * GST;
            uint4* dh = (uint4*)(nst + 0 * GPL + soff);
            uint4* dl = (uint4*)(nst + 1 * GPL + soff);
            uint4* db = (uint4*)(nst + 2 * GPL + soff);
            dh[0] = pah0; dh[1] = pah1;
            dl[0] = pal0; dl[1] = pal1;
            db[0] = pb0;  db[1] = pb1;
        }
        __syncthreads();
    }

    // epilogue: split to fp16 h/l planes; Q pre-scaled by 0.125*log2e
    const float scale = (z == 0) ? QSCALE : 1.0f;
    __half* oh = (z == 0) ? g_Qh : g_Kh;
    __half* ol = (z == 0) ? g_Ql : g_Kl;

#pragma unroll
    for (int mf = 0; mf < 4; mf++) {
        const int row = bm + wm * 64 + mf * 16 + g;
#pragma unroll
        for (int nf = 0; nf < 4; nf++) {
            const int col = bn + wn * 32 + nf * 8 + tig * 2;
            uint32_t hp, lp;
            split2x(acc[mf][nf][0] * scale, acc[mf][nf][1] * scale, hp, lp);
            *(uint32_t*)(oh + (size_t)row * D_MODEL + col) = hp;
            *(uint32_t*)(ol + (size_t)row * D_MODEL + col) = lp;
            split2x(acc[mf][nf][2] * scale, acc[mf][nf][3] * scale, hp, lp);
            *(uint32_t*)(oh + (size_t)(row + 8) * D_MODEL + col) = hp;
            *(uint32_t*)(ol + (size_t)(row + 8) * D_MODEL + col) = lp;
        }
    }
}

// ---------------- int8 GEMM (V-projection, O-projection) ----------------
// A = s1*A1 + (s1/192)*A2 (int8 planes), W ternary int8 (exact).
// Block 128x128, 8 warps (2x4), warp 64x32, k-chunks of 64 (2 IMMA k32 steps).
#define IBM 128
#define IBN 128
#define ICK 64
#define INCH (D_MODEL/ICK)   // 16
#define IA_ROW 144           // [a1:64B | a2:64B | pad:16B]; word stride 36 == 4 mod 32
#define IB_ROW 80            // [w:64B | pad:16B]; word stride 20 -> 4*(5g%8) pattern
#define IA_SZ (IBM*IA_ROW)   // 18432
#define IB_SZ (IBN*IB_ROW)   // 10240
#define ISTG (IA_SZ+IB_SZ)   // 28672
#define I8_SMEM (2*ISTG)     // 57344

__global__ __launch_bounds__(256) void gemm_i8_kernel(
    const char* __restrict__ A1, const char* __restrict__ A2,
    const char* __restrict__ W8, float* __restrict__ outF,
    int amax_idx, int mode)     // mode 0: -> g_Vh fp16; mode 1: -> fp32 outF
{
    extern __shared__ char ism[];

    const int tid  = threadIdx.x;
    const int lane = tid & 31;
    const int wid  = tid >> 5;
    const int wm   = wid & 1;
    const int wn   = wid >> 1;
    const int g    = lane >> 2;
    const int tig  = lane & 3;

    const int bm = blockIdx.y * IBM;
    const int bn = blockIdx.x * IBN;

    const int lr = tid >> 1;          // 0..127
    const int hh = tid & 1;           // 32-byte half
    const char* A1p = A1 + (size_t)(bm + lr) * D_MODEL + hh * 32;
    const char* A2p = A2 + (size_t)(bm + lr) * D_MODEL + hh * 32;
    const char* WPp = W8 + (size_t)(bn + lr) * D_MODEL + hh * 32;

    int acc1[4][4][4], acc2[4][4][4];
#pragma unroll
    for (int mf = 0; mf < 4; mf++)
#pragma unroll
        for (int nf = 0; nf < 4; nf++)
#pragma unroll
            for (int r = 0; r < 4; r++) { acc1[mf][nf][r] = 0; acc2[mf][nf][r] = 0; }

    uint4 p10 = *(const uint4*)(A1p);
    uint4 p11 = *(const uint4*)(A1p + 16);
    uint4 p20 = *(const uint4*)(A2p);
    uint4 p21 = *(const uint4*)(A2p + 16);
    uint4 pw0 = *(const uint4*)(WPp);
    uint4 pw1 = *(const uint4*)(WPp + 16);
    {
        char* as = ism + lr * IA_ROW;
        *(uint4*)(as + hh * 32)      = p10;
        *(uint4*)(as + hh * 32 + 16) = p11;
        *(uint4*)(as + 64 + hh * 32)      = p20;
        *(uint4*)(as + 64 + hh * 32 + 16) = p21;
        char* bs = ism + IA_SZ + lr * IB_ROW + hh * 32;
        *(uint4*)(bs)      = pw0;
        *(uint4*)(bs + 16) = pw1;
    }
    __syncthreads();

    for (int c = 0; c < INCH; c++) {
        const char* st = ism + (c & 1) * ISTG;

        if (c + 1 < INCH) {
            const int ko = (c + 1) * ICK;
            p10 = *(const uint4*)(A1p + ko);
            p11 = *(const uint4*)(A1p + ko + 16);
            p20 = *(const uint4*)(A2p + ko);
            p21 = *(const uint4*)(A2p + ko + 16);
            pw0 = *(const uint4*)(WPp + ko);
            pw1 = *(const uint4*)(WPp + ko + 16);
        }

#pragma unroll
        for (int s = 0; s < 2; s++) {
            uint32_t bf[4][2];
#pragma unroll
            for (int nf = 0; nf < 4; nf++) {
                const int n = wn * 32 + nf * 8 + g;
                const uint32_t* bp = (const uint32_t*)(st + IA_SZ + n * IB_ROW) + s * 8 + tig;
                bf[nf][0] = bp[0];
                bf[nf][1] = bp[4];
            }
#pragma unroll
            for (int mf = 0; mf < 4; mf++) {
                const int m = wm * 64 + mf * 16;
                const uint32_t* r0 = (const uint32_t*)(st + (m + g) * IA_ROW) + s * 8 + tig;
                const uint32_t* r1 = (const uint32_t*)(st + (m + g + 8) * IA_ROW) + s * 8 + tig;
                uint32_t a0 = r0[0],  a2v = r0[4];     // plane 1
                uint32_t a1 = r1[0],  a3v = r1[4];
                uint32_t c0 = r0[16], c2v = r0[20];    // plane 2 (byte +64 = word +16)
                uint32_t c1 = r1[16], c3v = r1[20];
#pragma unroll
                for (int nf = 0; nf < 4; nf++) {
                    mma_s8(acc1[mf][nf], a0, a1, a2v, a3v, bf[nf][0], bf[nf][1]);
                    mma_s8(acc2[mf][nf], c0, c1, c2v, c3v, bf[nf][0], bf[nf][1]);
                }
            }
        }

        if (c + 1 < INCH) {
            char* nst = ism + ((c + 1) & 1) * ISTG;
            char* as = nst + lr * IA_ROW;
            *(uint4*)(as + hh * 32)      = p10;
            *(uint4*)(as + hh * 32 + 16) = p11;
            *(uint4*)(as + 64 + hh * 32)      = p20;
            *(uint4*)(as + 64 + hh * 32 + 16) = p21;
            char* bs = nst + IA_SZ + lr * IB_ROW + hh * 32;
            *(uint4*)(bs)      = pw0;
            *(uint4*)(bs + 16) = pw1;
        }
        __syncthreads();
    }

    // epilogue
    const float amax = __int_as_float(g_amaxb[amax_idx]);
    const float s1 = amax * (1.0f / 127.0f);
    const float s2 = s1 * (1.0f / 192.0f);

#pragma unroll
    for (int mf = 0; mf < 4; mf++) {
        const int row = bm + wm * 64 + mf * 16 + g;
#pragma unroll
        for (int nf = 0; nf < 4; nf++) {
            const int col = bn + wn * 32 + nf * 8 + tig * 2;
            float v0 = s1 * (float)acc1[mf][nf][0] + s2 * (float)acc2[mf][nf][0];
            float v1 = s1 * (float)acc1[mf][nf][1] + s2 * (float)acc2[mf][nf][1];
            float v2 = s1 * (float)acc1[mf][nf][2] + s2 * (float)acc2[mf][nf][2];
            float v3 = s1 * (float)acc1[mf][nf][3] + s2 * (float)acc2[mf][nf][3];
            if (mode == 0) {
                *(uint32_t*)(g_Vh + (size_t)row * D_MODEL + col)       = pack_h2(v0, v1);
                *(uint32_t*)(g_Vh + (size_t)(row + 8) * D_MODEL + col) = pack_h2(v2, v3);
            } else {
                *(float2*)&outF[(size_t)row * D_MODEL + col]       = make_float2(v0, v1);
                *(float2*)&outF[(size_t)(row + 8) * D_MODEL + col] = make_float2(v2, v3);
            }
        }
    }
}

// ---------------- flash: double-buffered KV + register-repacked P (exp2) ----------------
#define FQT 128
#define FKT 64
#define NT  (SEQ/FKT)
#define ROWB 144
#define QH_OFF 0
#define QL_OFF (128*ROWB)
#define ST_OFF (2*128*ROWB)
#define ST_SZ  (3*64*ROWB)
#define FLASH_SMEM (ST_OFF + 2*ST_SZ)   // 92160

__global__ __launch_bounds__(256, 2) void flash_h4_kernel()
{
    extern __shared__ char fsm[];

    const int tid  = threadIdx.x;
    const int lane = tid & 31;
    const int wid  = tid >> 5;
    const int g    = lane >> 2;
    const int tig  = lane & 3;

    const int qb = blockIdx.x;
    const int h  = blockIdx.y;
    const int b  = blockIdx.z;
    const size_t qrow0 = (size_t)b * SEQ + (size_t)qb * FQT;
    const int col0 = h * HDIM;

    {
        const int r  = tid >> 1;
        const int dq = (tid & 1) * 32;
        const __half* sh = g_Qh + (qrow0 + r) * D_MODEL + col0 + dq;
        const __half* sl = g_Ql + (qrow0 + r) * D_MODEL + col0 + dq;
        uint4* dh = (uint4*)(fsm + QH_OFF + r * ROWB + dq * 2);
        uint4* dl = (uint4*)(fsm + QL_OFF + r * ROWB + dq * 2);
#pragma unroll
        for (int p = 0; p < 4; p++) {
            dh[p] = *(const uint4*)(sh + 8 * p);
            dl[p] = *(const uint4*)(sl + 8 * p);
        }
    }

    const int rowA = wid * 16 + g;

    const int keyK = tid >> 2;
    const int d0K  = (tid & 3) * 16;
    const int keyV = tid & 63;
    const int d0V  = (tid >> 6) * 16;
    const size_t kvbase = (size_t)b * SEQ * D_MODEL + col0;

    float o_acc[8][4];
#pragma unroll
    for (int nf = 0; nf < 8; nf++)
#pragma unroll
        for (int r = 0; r < 4; r++) o_acc[nf][r] = 0.0f;
    float m0 = -INFINITY, m1 = -INFINITY;
    float l0s = 0.0f, l1s = 0.0f;

    uint4 kh0, kh1, kl0, kl1, vv0, vv1;
    {
        const size_t sk = kvbase + (size_t)keyK * D_MODEL + d0K;
        kh0 = *(const uint4*)(g_Kh + sk);
        kh1 = *(const uint4*)(g_Kh + sk + 8);
        kl0 = *(const uint4*)(g_Kl + sk);
        kl1 = *(const uint4*)(g_Kl + sk + 8);
        const size_t sv = kvbase + (size_t)keyV * D_MODEL + d0V;
        vv0 = *(const uint4*)(g_Vh + sv);
        vv1 = *(const uint4*)(g_Vh + sv + 8);
    }
    {
        char* st = fsm + ST_OFF;
        uint4* kh = (uint4*)(st + keyK * ROWB + d0K * 2);
        uint4* kl = (uint4*)(st + 64 * ROWB + keyK * ROWB + d0K * 2);
        kh[0] = kh0; kh[1] = kh1;
        kl[0] = kl0; kl[1] = kl1;
        char* vt = st + 128 * ROWB;
        const __half* vh = (const __half*)&vv0;
#pragma unroll
        for (int j = 0; j < 8; j++)
            *(__half*)(vt + (d0V + j) * ROWB + keyV * 2) = vh[j];
        vh = (const __half*)&vv1;
#pragma unroll
        for (int j = 0; j < 8; j++)
            *(__half*)(vt + (d0V + 8 + j) * ROWB + keyV * 2) = vh[j];
    }
    __syncthreads();

    for (int kb = 0; kb < NT; kb++) {
        const char* st = fsm + ST_OFF + (kb & 1) * ST_SZ;

        if (kb + 1 < NT) {
            const size_t sk = kvbase + ((size_t)(kb + 1) * FKT + keyK) * D_MODEL + d0K;
            kh0 = *(const uint4*)(g_Kh + sk);
            kh1 = *(const uint4*)(g_Kh + sk + 8);
            kl0 = *(const uint4*)(g_Kl + sk);
            kl1 = *(const uint4*)(g_Kl + sk + 8);
            const size_t sv = kvbase + ((size_t)(kb + 1) * FKT + keyV) * D_MODEL + d0V;
            vv0 = *(const uint4*)(g_Vh + sv);
            vv1 = *(const uint4*)(g_Vh + sv + 8);
        }

        float s_acc[8][4];
#pragma unroll
        for (int nf = 0; nf < 8; nf++)
#pragma unroll
            for (int r = 0; r < 4; r++) s_acc[nf][r] = 0.0f;

#pragma unroll
        for (int s = 0; s < 4; s++) {
            const uint32_t* qh0p = (const uint32_t*)(fsm + QH_OFF + rowA * ROWB) + s * 8 + tig;
            const uint32_t* qh1p = (const uint32_t*)(fsm + QH_OFF + (rowA + 8) * ROWB) + s * 8 + tig;
            const uint32_t* ql0p = (const uint32_t*)(fsm + QL_OFF + rowA * ROWB) + s * 8 + tig;
            const uint32_t* ql1p = (const uint32_t*)(fsm + QL_OFF + (rowA + 8) * ROWB) + s * 8 + tig;
            uint32_t ah0 = qh0p[0], ah2 = qh0p[4];
            uint32_t ah1 = qh1p[0], ah3 = qh1p[4];
            uint32_t al0 = ql0p[0], al2 = ql0p[4];
            uint32_t al1 = ql1p[0], al3 = ql1p[4];
#pragma unroll
            for (int nf = 0; nf < 8; nf++) {
                const uint32_t* khp = (const uint32_t*)(st + (nf * 8 + g) * ROWB) + s * 8 + tig;
                const uint32_t* klp = (const uint32_t*)(st + 64 * ROWB + (nf * 8 + g) * ROWB) + s * 8 + tig;
                uint32_t bh0 = khp[0], bh1 = khp[4];
                uint32_t bl0 = klp[0], bl1 = klp[4];
                mma_f16(s_acc[nf], ah0, ah1, ah2, ah3, bh0, bh1);
                mma_f16(s_acc[nf], al0, al1, al2, al3, bh0, bh1);
                mma_f16(s_acc[nf], ah0, ah1, ah2, ah3, bl0, bl1);
            }
        }

        // ---- online softmax in log2 domain (Q pre-scaled by log2e) ----
        float mx0 = m0, mx1 = m1;
#pragma unroll
        for (int nf = 0; nf < 8; nf++) {
            mx0 = fmaxf(mx0, fmaxf(s_acc[nf][0], s_acc[nf][1]));
            mx1 = fmaxf(mx1, fmaxf(s_acc[nf][2], s_acc[nf][3]));
        }
        mx0 = fmaxf(mx0, __shfl_xor_sync(0xffffffff, mx0, 1));
        mx0 = fmaxf(mx0, __shfl_xor_sync(0xffffffff, mx0, 2));
        mx1 = fmaxf(mx1, __shfl_xor_sync(0xffffffff, mx1, 1));
        mx1 = fmaxf(mx1, __shfl_xor_sync(0xffffffff, mx1, 2));
        float sc0 = exp2f(m0 - mx0);
        float sc1 = exp2f(m1 - mx1);
        m0 = mx0; m1 = mx1;
        float sum0 = 0.0f, sum1 = 0.0f;
#pragma unroll
        for (int nf = 0; nf < 8; nf++) {
            s_acc[nf][0] = exp2f(s_acc[nf][0] - mx0);
            s_acc[nf][1] = exp2f(s_acc[nf][1] - mx0);
            s_acc[nf][2] = exp2f(s_acc[nf][2] - mx1);
            s_acc[nf][3] = exp2f(s_acc[nf][3] - mx1);
            sum0 += s_acc[nf][0] + s_acc[nf][1];
            sum1 += s_acc[nf][2] + s_acc[nf][3];
        }
        sum0 += __shfl_xor_sync(0xffffffff, sum0, 1);
        sum0 += __shfl_xor_sync(0xffffffff, sum0, 2);
        sum1 += __shfl_xor_sync(0xffffffff, sum1, 1);
        sum1 += __shfl_xor_sync(0xffffffff, sum1, 2);
        l0s = l0s * sc0 + sum0;
        l1s = l1s * sc1 + sum1;
#pragma unroll
        for (int nf = 0; nf < 8; nf++) {
            o_acc[nf][0] *= sc0; o_acc[nf][1] *= sc0;
            o_acc[nf][2] *= sc1; o_acc[nf][3] *= sc1;
        }

        // ---- O += P @ V : register repack, 1 term ----
#pragma unroll
        for (int s = 0; s < 4; s++) {
            uint32_t pa0 = pack_h2(s_acc[2 * s][0],     s_acc[2 * s][1]);
            uint32_t pa1 = pack_h2(s_acc[2 * s][2],     s_acc[2 * s][3]);
            uint32_t pa2 = pack_h2(s_acc[2 * s + 1][0], s_acc[2 * s + 1][1]);
            uint32_t pa3 = pack_h2(s_acc[2 * s + 1][2], s_acc[2 * s + 1][3]);
#pragma unroll
            for (int nf = 0; nf < 8; nf++) {
                const uint32_t* vp = (const uint32_t*)(st + 128 * ROWB + (nf * 8 + g) * ROWB) + s * 8 + tig;
                mma_f16(o_acc[nf], pa0, pa1, pa2, pa3, vp[0], vp[4]);
            }
        }

        if (kb + 1 < NT) {
            char* nst = fsm + ST_OFF + ((kb + 1) & 1) * ST_SZ;
            uint4* kh = (uint4*)(nst + keyK * ROWB + d0K * 2);
            uint4* kl = (uint4*)(nst + 64 * ROWB + keyK * ROWB + d0K * 2);
            kh[0] = kh0; kh[1] = kh1;
            kl[0] = kl0; kl[1] = kl1;
            char* vt = nst + 128 * ROWB;
            const __half* vh = (const __half*)&vv0;
#pragma unroll
            for (int j = 0; j < 8; j++)
                *(__half*)(vt + (d0V + j) * ROWB + keyV * 2) = vh[j];
            vh = (const __half*)&vv1;
#pragma unroll
            for (int j = 0; j < 8; j++)
                *(__half*)(vt + (d0V + 8 + j) * ROWB + keyV * 2) = vh[j];
        }
        __syncthreads();
    }

    const float inv0 = 1.0f / l0s;
    const float inv1 = 1.0f / l1s;
#pragma unroll
    for (int nf = 0; nf < 8; nf++) {
        const int col = col0 + nf * 8 + tig * 2;
        uint32_t hp, lp;
        split2x(o_acc[nf][0] * inv0, o_acc[nf][1] * inv0, hp, lp);
        *(uint32_t*)(g_Oh + (qrow0 + rowA) * D_MODEL + col) = hp;
        *(uint32_t*)(g_Ol + (qrow0 + rowA) * D_MODEL + col) = lp;
        split2x(o_acc[nf][2] * inv1, o_acc[nf][3] * inv1, hp, lp);
        *(uint32_t*)(g_Oh + (qrow0 + rowA + 8) * D_MODEL + col) = hp;
        *(uint32_t*)(g_Ol + (qrow0 + rowA + 8) * D_MODEL + col) = lp;
    }
}

// ---------------- host launch ----------------
extern "C" void kernel_launch(void* const* d_in, const int* in_sizes, int n_in,
                              void* d_out, int out_size)
{
    const float* query = (const float*)d_in[0];
    const float* key   = (const float*)d_in[1];
    const float* value = (const float*)d_in[2];
    const float* w_q   = (const float*)d_in[3];
    const float* w_k   = (const float*)d_in[4];
    const float* w_v   = (const float*)d_in[5];
    const float* w_o   = (const float*)d_in[6];
    float* out = (float*)d_out;

    char* pV8a; cudaGetSymbolAddress((void**)&pV8a, g_V8a);
    char* pV8b; cudaGetSymbolAddress((void**)&pV8b, g_V8b);
    char* pO8a; cudaGetSymbolAddress((void**)&pO8a, g_O8a);
    char* pO8b; cudaGetSymbolAddress((void**)&pO8b, g_O8b);
    char* pW8;  cudaGetSymbolAddress((void**)&pW8,  g_W8);

    cudaFuncSetAttribute(flash_h4_kernel,
                         cudaFuncAttributeMaxDynamicSharedMemorySize, FLASH_SMEM);
    cudaFuncSetAttribute(gemm_h2_kernel,
                         cudaFuncAttributeMaxDynamicSharedMemorySize, GEMM_SMEM);
    cudaFuncSetAttribute(gemm_i8_kernel,
                         cudaFuncAttributeMaxDynamicSharedMemorySize, I8_SMEM);

    zero_sums_kernel<<<1, 32>>>();
    abssum_kernel<<<dim3(128, 4), 256>>>(w_q, w_k, w_v, w_o);
    ternarize_kernel<<<dim3(D_MODEL * D_MODEL / 256, 4), 256>>>(w_q, w_k, w_v, w_o);

    // q,k -> fp16 h/l planes; value -> int8 planes
    presplit_kernel<<<dim3(PLN / 1024, 2), 256>>>(query, key);
    amax_f32_kernel<<<PLN / 1024, 256>>>(value, 0);
    quant_f32_kernel<<<PLN / 1024, 256>>>(value, pV8a, pV8b, 0);

    // Q,K projections (fp16 split MMA)
    gemm_h2_kernel<<<dim3(D_MODEL / GBN, MROWS / GBM, 2), 256, GEMM_SMEM>>>();
    // V projection (int8 IMMA) -> g_Vh
    gemm_i8_kernel<<<dim3(D_MODEL / IBN, MROWS / IBM), 256, I8_SMEM>>>(
        pV8a, pV8b, pW8 + 0 * (size_t)(D_MODEL * D_MODEL), nullptr, 0, 0);

    flash_h4_kernel<<<dim3(SEQ / FQT, NHEADS, BATCH), 256, FLASH_SMEM>>>();

    // O -> int8 planes, then output projection (int8 IMMA) -> fp32 out
    amax_O_kernel<<<PLN / 1024, 256>>>();
    quant_O_kernel<<<PLN / 1024, 256>>>();
    gemm_i8_kernel<<<dim3(D_MODEL / IBN, MROWS / IBM), 256, I8_SMEM>>>(
        pO8a, pO8b, pW8 + 1 * (size_t)(D_MODEL * D_MODEL), out, 1, 1);
}

// round 12
// speedup vs baseline: 1.3391x; 1.3391x over previous
#include <cuda_runtime.h>
#include <cuda_fp16.h>
#include <math.h>
#include <stdint.h>

#define D_MODEL 1024
#define NHEADS  16
#define HDIM    64
#define BATCH   2
#define SEQ     2048
#define MROWS   (BATCH*SEQ)   // 4096
#define PLN     (MROWS*D_MODEL)

// ---------------- device scratch ----------------
__device__ __align__(128) float g_sums[4];
__device__ __align__(128) __half g_Wh[4][D_MODEL*D_MODEL];
__device__ __align__(128) __half g_Xh[3][PLN];
__device__ __align__(128) __half g_Xl[3][PLN];
__device__ __align__(128) __half g_Qh[PLN];   // pre-scaled by 0.125*log2(e)
__device__ __align__(128) __half g_Ql[PLN];
__device__ __align__(128) __half g_Kh[PLN];
__device__ __align__(128) __half g_Kl[PLN];
__device__ __align__(128) __half g_Vh[PLN];
__device__ __align__(128) __half g_Oh[PLN];
__device__ __align__(128) __half g_Ol[PLN];

#define QSCALE 0.18033688011112042f   // 0.125 * log2(e)

// ---------------- helpers ----------------
__device__ __forceinline__ void mma_f16(float* c,
    uint32_t a0, uint32_t a1, uint32_t a2, uint32_t a3,
    uint32_t b0, uint32_t b1)
{
    asm volatile(
        "mma.sync.aligned.m16n8k16.row.col.f32.f16.f16.f32 "
        "{%0,%1,%2,%3}, {%4,%5,%6,%7}, {%8,%9}, {%0,%1,%2,%3};"
        : "+f"(c[0]), "+f"(c[1]), "+f"(c[2]), "+f"(c[3])
        : "r"(a0), "r"(a1), "r"(a2), "r"(a3), "r"(b0), "r"(b1));
}

__device__ __forceinline__ void split2x(float x, float y, uint32_t& hp, uint32_t& lp) {
    __half hx = __float2half_rn(x);
    __half hy = __float2half_rn(y);
    __half lx = __float2half_rn(x - __half2float(hx));
    __half ly = __float2half_rn(y - __half2float(hy));
    __half2 h2 = __halves2half2(hx, hy);
    __half2 l2 = __halves2half2(lx, ly);
    hp = *reinterpret_cast<uint32_t*>(&h2);
    lp = *reinterpret_cast<uint32_t*>(&l2);
}
__device__ __forceinline__ uint32_t pack_h2(float x, float y) {
    __half2 t = __floats2half2_rn(x, y);
    return *reinterpret_cast<uint32_t*>(&t);
}

// ---------------- ternarize ----------------
__global__ void zero_sums_kernel() {
    if (threadIdx.x < 4) g_sums[threadIdx.x] = 0.0f;
}

__global__ __launch_bounds__(256) void abssum_kernel(
    const float* __restrict__ w0, const float* __restrict__ w1,
    const float* __restrict__ w2, const float* __restrict__ w3)
{
    const float* w = (blockIdx.y == 0) ? w0 : (blockIdx.y == 1) ? w1
                     : (blockIdx.y == 2) ? w2 : w3;
    const int n = D_MODEL * D_MODEL;
    float s = 0.0f;
    for (int i = blockIdx.x * blockDim.x + threadIdx.x; i < n;
         i += gridDim.x * blockDim.x)
        s += fabsf(w[i]);
    __shared__ float red[256];
    red[threadIdx.x] = s;
    __syncthreads();
    for (int o = 128; o > 0; o >>= 1) {
        if (threadIdx.x < o) red[threadIdx.x] += red[threadIdx.x + o];
        __syncthreads();
    }
    if (threadIdx.x == 0) atomicAdd(&g_sums[blockIdx.y], red[0]);
}

__global__ __launch_bounds__(256) void ternarize_kernel(
    const float* __restrict__ w0, const float* __restrict__ w1,
    const float* __restrict__ w2, const float* __restrict__ w3)
{
    const int m = blockIdx.y;
    const float* w = (m == 0) ? w0 : (m == 1) ? w1 : (m == 2) ? w2 : w3;
    const float mean = g_sums[m] * (1.0f / (float)(D_MODEL * D_MODEL));
    int i = blockIdx.x * blockDim.x + threadIdx.x;
    float v = w[i];
    float t = (fabsf(v) > mean) ? (v > 0.0f ? 1.0f : -1.0f) : 0.0f;
    g_Wh[m][i] = __float2half_rn(t);
}

// ---------------- pre-split inputs ----------------
__global__ __launch_bounds__(256) void presplit_kernel(
    const float* __restrict__ q, const float* __restrict__ k,
    const float* __restrict__ v)
{
    const int z = blockIdx.y;
    const float* src = (z == 0) ? q : (z == 1) ? k : v;
    __half* hP = g_Xh[z];
    __half* lP = g_Xl[z];
    const int i = (blockIdx.x * blockDim.x + threadIdx.x) * 4;
    float4 val = *(const float4*)(src + i);
    uint32_t h0, l0, h1, l1;
    split2x(val.x, val.y, h0, l0);
    split2x(val.z, val.w, h1, l1);
    *(uint32_t*)(hP + i)     = h0;
    *(uint32_t*)(hP + i + 2) = h1;
    *(uint32_t*)(lP + i)     = l0;
    *(uint32_t*)(lP + i + 2) = l1;
}

// ---------------- GEMM: double-buffered, one sync per chunk ----------------
#define GBM 128
#define GBN 128
#define GBK 32
#define SRH 40
#define NCH (D_MODEL/GBK)
#define GPL (GBM*SRH*2)        // 10240
#define GST (3*GPL)            // 30720
#define GEMM_SMEM (2*GST)      // 61440

__global__ __launch_bounds__(256, 2) void gemm_h2_kernel(float* __restrict__ outF, int which)
{
    extern __shared__ char gsm[];

    const int tid  = threadIdx.x;
    const int lane = tid & 31;
    const int wid  = tid >> 5;
    const int wm   = wid & 1;
    const int wn   = wid >> 1;
    const int g    = lane >> 2;
    const int tig  = lane & 3;

    const int z  = blockIdx.z;
    const __half *Ah_, *Al_, *W_;
    if (which == 0) {
        Ah_ = g_Xh[z]; Al_ = g_Xl[z]; W_ = g_Wh[z];
    } else {
        Ah_ = g_Oh; Al_ = g_Ol; W_ = g_Wh[3];
    }

    const int bm = blockIdx.y * GBM;
    const int bn = blockIdx.x * GBN;

    const int lr = tid >> 1;
    const int lk = (tid & 1) * 16;
    const __half* AhP = Ah_ + (size_t)(bm + lr) * D_MODEL + lk;
    const __half* AlP = Al_ + (size_t)(bm + lr) * D_MODEL + lk;
    const __half* WP  = W_  + (size_t)(bn + lr) * D_MODEL + lk;
    const int soff = lr * (SRH * 2) + lk * 2;

    float acc[4][4][4];
#pragma unroll
    for (int mf = 0; mf < 4; mf++)
#pragma unroll
        for (int nf = 0; nf < 4; nf++)
#pragma unroll
            for (int r = 0; r < 4; r++) acc[mf][nf][r] = 0.0f;

    uint4 pah0 = *(const uint4*)(AhP);
    uint4 pah1 = *(const uint4*)(AhP + 8);
    uint4 pal0 = *(const uint4*)(AlP);
    uint4 pal1 = *(const uint4*)(AlP + 8);
    uint4 pb0  = *(const uint4*)(WP);
    uint4 pb1  = *(const uint4*)(WP + 8);
    {
        uint4* dh = (uint4*)(gsm + 0 * GST + 0 * GPL + soff);
        uint4* dl = (uint4*)(gsm + 0 * GST + 1 * GPL + soff);
        uint4* db = (uint4*)(gsm + 0 * GST + 2 * GPL + soff);
        dh[0] = pah0; dh[1] = pah1;
        dl[0] = pal0; dl[1] = pal1;
        db[0] = pb0;  db[1] = pb1;
    }
    __syncthreads();

    for (int c = 0; c < NCH; c++) {
        const char* st = gsm + (c & 1) * GST;

        if (c + 1 < NCH) {
            const int ko = (c + 1) * GBK;
            pah0 = *(const uint4*)(AhP + ko);
            pah1 = *(const uint4*)(AhP + ko + 8);
            pal0 = *(const uint4*)(AlP + ko);
            pal1 = *(const uint4*)(AlP + ko + 8);
            pb0  = *(const uint4*)(WP + ko);
            pb1  = *(const uint4*)(WP + ko + 8);
        }

#pragma unroll
        for (int s = 0; s < 2; s++) {
            uint32_t bf[4][2];
#pragma unroll
            for (int nf = 0; nf < 4; nf++) {
                const int n = wn * 32 + nf * 8 + g;
                const uint32_t* bp = (const uint32_t*)(st + 2 * GPL + n * SRH * 2) + s * 8 + tig;
                bf[nf][0] = bp[0];
                bf[nf][1] = bp[4];
            }
#pragma unroll
            for (int mf = 0; mf < 4; mf++) {
                const int m = wm * 64 + mf * 16;
                const uint32_t* ah0p = (const uint32_t*)(st + 0 * GPL + (m + g) * SRH * 2) + s * 8 + tig;
                const uint32_t* ah1p = (const uint32_t*)(st + 0 * GPL + (m + g + 8) * SRH * 2) + s * 8 + tig;
                const uint32_t* al0p = (const uint32_t*)(st + 1 * GPL + (m + g) * SRH * 2) + s * 8 + tig;
                const uint32_t* al1p = (const uint32_t*)(st + 1 * GPL + (m + g + 8) * SRH * 2) + s * 8 + tig;
                uint32_t h0 = ah0p[0], h2 = ah0p[4];
                uint32_t h1 = ah1p[0], h3 = ah1p[4];
                uint32_t l0 = al0p[0], l2 = al0p[4];
                uint32_t l1 = al1p[0], l3 = al1p[4];
#pragma unroll
                for (int nf = 0; nf < 4; nf++) {
                    mma_f16(acc[mf][nf], l0, l1, l2, l3, bf[nf][0], bf[nf][1]);
                    mma_f16(acc[mf][nf], h0, h1, h2, h3, bf[nf][0], bf[nf][1]);
                }
            }
        }

        if (c + 1 < NCH) {
            char* nst = gsm + ((c + 1) & 1) * GST;
            uint4* dh = (uint4*)(nst + 0 * GPL + soff);
            uint4* dl = (uint4*)(nst + 1 * GPL + soff);
            uint4* db = (uint4*)(nst + 2 * GPL + soff);
            dh[0] = pah0; dh[1] = pah1;
            dl[0] = pal0; dl[1] = pal1;
            db[0] = pb0;  db[1] = pb1;
        }
        __syncthreads();
    }

    const int mode = (which == 1) ? 2 : (z == 2) ? 1 : 0;
    const float scale = (which == 0 && z == 0) ? QSCALE : 1.0f;
    __half* oh = nullptr;
    __half* ol = nullptr;
    if (which == 0) {
        if (z == 0)      { oh = g_Qh; ol = g_Ql; }
        else if (z == 1) { oh = g_Kh; ol = g_Kl; }
        else             { oh = g_Vh; }
    }

#pragma unroll
    for (int mf = 0; mf < 4; mf++) {
        const int row = bm + wm * 64 + mf * 16 + g;
#pragma unroll
        for (int nf = 0; nf < 4; nf++) {
            const int col = bn + wn * 32 + nf * 8 + tig * 2;
            if (mode == 2) {
                *(float2*)&outF[(size_t)row * D_MODEL + col] =
                    make_float2(acc[mf][nf][0], acc[mf][nf][1]);
                *(float2*)&outF[(size_t)(row + 8) * D_MODEL + col] =
                    make_float2(acc[mf][nf][2], acc[mf][nf][3]);
            } else if (mode == 0) {
                uint32_t hp, lp;
                split2x(acc[mf][nf][0] * scale, acc[mf][nf][1] * scale, hp, lp);
                *(uint32_t*)(oh + (size_t)row * D_MODEL + col) = hp;
                *(uint32_t*)(ol + (size_t)row * D_MODEL + col) = lp;
                split2x(acc[mf][nf][2] * scale, acc[mf][nf][3] * scale, hp, lp);
                *(uint32_t*)(oh + (size_t)(row + 8) * D_MODEL + col) = hp;
                *(uint32_t*)(ol + (size_t)(row + 8) * D_MODEL + col) = lp;
            } else {
                __half2 v0 = __floats2half2_rn(acc[mf][nf][0], acc[mf][nf][1]);
                __half2 v1 = __floats2half2_rn(acc[mf][nf][2], acc[mf][nf][3]);
                *(uint32_t*)(oh + (size_t)row * D_MODEL + col) = *(uint32_t*)&v0;
                *(uint32_t*)(oh + (size_t)(row + 8) * D_MODEL + col) = *(uint32_t*)&v1;
            }
        }
    }
}

// ---------------- flash: double-buffered KV + register-repacked P (exp2) ----------------
#define FQT 128
#define FKT 64
#define NT  (SEQ/FKT)
#define ROWB 144
#define QH_OFF 0
#define QL_OFF (128*ROWB)
#define ST_OFF (2*128*ROWB)      // 36864
#define ST_SZ  (3*64*ROWB)       // 27648
#define FLASH_SMEM (ST_OFF + 2*ST_SZ)   // 92160 -> 2 blocks/SM

__global__ __launch_bounds__(256, 2) void flash_h4_kernel()
{
    extern __shared__ char fsm[];

    const int tid  = threadIdx.x;
    const int lane = tid & 31;
    const int wid  = tid >> 5;
    const int g    = lane >> 2;
    const int tig  = lane & 3;

    const int qb = blockIdx.x;
    const int h  = blockIdx.y;
    const int b  = blockIdx.z;
    const size_t qrow0 = (size_t)b * SEQ + (size_t)qb * FQT;
    const int col0 = h * HDIM;

    // ---- load Q tile planes (pre-scaled by 0.125*log2e) ----
    {
        const int r  = tid >> 1;
        const int dq = (tid & 1) * 32;
        const __half* sh = g_Qh + (qrow0 + r) * D_MODEL + col0 + dq;
        const __half* sl = g_Ql + (qrow0 + r) * D_MODEL + col0 + dq;
        uint4* dh = (uint4*)(fsm + QH_OFF + r * ROWB + dq * 2);
        uint4* dl = (uint4*)(fsm + QL_OFF + r * ROWB + dq * 2);
#pragma unroll
        for (int p = 0; p < 4; p++) {
            dh[p] = *(const uint4*)(sh + 8 * p);
            dl[p] = *(const uint4*)(sl + 8 * p);
        }
    }

    const int rowA = wid * 16 + g;

    const int keyK = tid >> 2;
    const int d0K  = (tid & 3) * 16;
    const int keyV = tid & 63;
    const int d0V  = (tid >> 6) * 16;
    const size_t kvbase = (size_t)b * SEQ * D_MODEL + col0;

    float o_acc[8][4];
#pragma unroll
    for (int nf = 0; nf < 8; nf++)
#pragma unroll
        for (int r = 0; r < 4; r++) o_acc[nf][r] = 0.0f;
    float m0 = -INFINITY, m1 = -INFINITY;
    float l0s = 0.0f, l1s = 0.0f;

    uint4 kh0, kh1, kl0, kl1, vv0, vv1;
    {
        const size_t sk = kvbase + (size_t)keyK * D_MODEL + d0K;
        kh0 = *(const uint4*)(g_Kh + sk);
        kh1 = *(const uint4*)(g_Kh + sk + 8);
        kl0 = *(const uint4*)(g_Kl + sk);
        kl1 = *(const uint4*)(g_Kl + sk + 8);
        const size_t sv = kvbase + (size_t)keyV * D_MODEL + d0V;
        vv0 = *(const uint4*)(g_Vh + sv);
        vv1 = *(const uint4*)(g_Vh + sv + 8);
    }
    {
        char* st = fsm + ST_OFF;
        uint4* kh = (uint4*)(st + keyK * ROWB + d0K * 2);
        uint4* kl = (uint4*)(st + 64 * ROWB + keyK * ROWB + d0K * 2);
        kh[0] = kh0; kh[1] = kh1;
        kl[0] = kl0; kl[1] = kl1;
        char* vt = st + 128 * ROWB;
        const __half* vh = (const __half*)&vv0;
#pragma unroll
        for (int j = 0; j < 8; j++)
            *(__half*)(vt + (d0V + j) * ROWB + keyV * 2) = vh[j];
        vh = (const __half*)&vv1;
#pragma unroll
        for (int j = 0; j < 8; j++)
            *(__half*)(vt + (d0V + 8 + j) * ROWB + keyV * 2) = vh[j];
    }
    __syncthreads();

    for (int kb = 0; kb < NT; kb++) {
        const char* st = fsm + ST_OFF + (kb & 1) * ST_SZ;

        if (kb + 1 < NT) {
            const size_t sk = kvbase + ((size_t)(kb + 1) * FKT + keyK) * D_MODEL + d0K;
            kh0 = *(const uint4*)(g_Kh + sk);
            kh1 = *(const uint4*)(g_Kh + sk + 8);
            kl0 = *(const uint4*)(g_Kl + sk);
            kl1 = *(const uint4*)(g_Kl + sk + 8);
            const size_t sv = kvbase + ((size_t)(kb + 1) * FKT + keyV) * D_MODEL + d0V;
            vv0 = *(const uint4*)(g_Vh + sv);
            vv1 = *(const uint4*)(g_Vh + sv + 8);
        }

        float s_acc[8][4];
#pragma unroll
        for (int nf = 0; nf < 8; nf++)
#pragma unroll
            for (int r = 0; r < 4; r++) s_acc[nf][r] = 0.0f;

#pragma unroll
        for (int s = 0; s < 4; s++) {
            const uint32_t* qh0p = (const uint32_t*)(fsm + QH_OFF + rowA * ROWB) + s * 8 + tig;
            const uint32_t* qh1p = (const uint32_t*)(fsm + QH_OFF + (rowA + 8) * ROWB) + s * 8 + tig;
            const uint32_t* ql0p = (const uint32_t*)(fsm + QL_OFF + rowA * ROWB) + s * 8 + tig;
            const uint32_t* ql1p = (const uint32_t*)(fsm + QL_OFF + (rowA + 8) * ROWB) + s * 8 + tig;
            uint32_t ah0 = qh0p[0], ah2 = qh0p[4];
            uint32_t ah1 = qh1p[0], ah3 = qh1p[4];
            uint32_t al0 = ql0p[0], al2 = ql0p[4];
            uint32_t al1 = ql1p[0], al3 = ql1p[4];
#pragma unroll
            for (int nf = 0; nf < 8; nf++) {
                const uint32_t* khp = (const uint32_t*)(st + (nf * 8 + g) * ROWB) + s * 8 + tig;
                const uint32_t* klp = (const uint32_t*)(st + 64 * ROWB + (nf * 8 + g) * ROWB) + s * 8 + tig;
                uint32_t bh0 = khp[0], bh1 = khp[4];
                uint32_t bl0 = klp[0], bl1 = klp[4];
                mma_f16(s_acc[nf], ah0, ah1, ah2, ah3, bh0, bh1);
                mma_f16(s_acc[nf], al0, al1, al2, al3, bh0, bh1);
                mma_f16(s_acc[nf], ah0, ah1, ah2, ah3, bl0, bl1);
            }
        }

        // ---- online softmax in log2 domain ----
        float mx0 = m0, mx1 = m1;
#pragma unroll
        for (int nf = 0; nf < 8; nf++) {
            mx0 = fmaxf(mx0, fmaxf(s_acc[nf][0], s_acc[nf][1]));
            mx1 = fmaxf(mx1, fmaxf(s_acc[nf][2], s_acc[nf][3]));
        }
        mx0 = fmaxf(mx0, __shfl_xor_sync(0xffffffff, mx0, 1));
        mx0 = fmaxf(mx0, __shfl_xor_sync(0xffffffff, mx0, 2));
        mx1 = fmaxf(mx1, __shfl_xor_sync(0xffffffff, mx1, 1));
        mx1 = fmaxf(mx1, __shfl_xor_sync(0xffffffff, mx1, 2));
        float sc0 = exp2f(m0 - mx0);
        float sc1 = exp2f(m1 - mx1);
        m0 = mx0; m1 = mx1;
        float sum0 = 0.0f, sum1 = 0.0f;
#pragma unroll
        for (int nf = 0; nf < 8; nf++) {
            s_acc[nf][0] = exp2f(s_acc[nf][0] - mx0);
            s_acc[nf][1] = exp2f(s_acc[nf][1] - mx0);
            s_acc[nf][2] = exp2f(s_acc[nf][2] - mx1);
            s_acc[nf][3] = exp2f(s_acc[nf][3] - mx1);
            sum0 += s_acc[nf][0] + s_acc[nf][1];
            sum1 += s_acc[nf][2] + s_acc[nf][3];
        }
        sum0 += __shfl_xor_sync(0xffffffff, sum0, 1);
        sum0 += __shfl_xor_sync(0xffffffff, sum0, 2);
        sum1 += __shfl_xor_sync(0xffffffff, sum1, 1);
        sum1 += __shfl_xor_sync(0xffffffff, sum1, 2);
        l0s = l0s * sc0 + sum0;
        l1s = l1s * sc1 + sum1;
#pragma unroll
        for (int nf = 0; nf < 8; nf++) {
            o_acc[nf][0] *= sc0; o_acc[nf][1] *= sc0;
            o_acc[nf][2] *= sc1; o_acc[nf][3] *= sc1;
        }

        // ---- O += P @ V : register repack (C-frag -> A-frag), 1 term ----
#pragma unroll
        for (int s = 0; s < 4; s++) {
            uint32_t pa0 = pack_h2(s_acc[2 * s][0],     s_acc[2 * s][1]);
            uint32_t pa1 = pack_h2(s_acc[2 * s][2],     s_acc[2 * s][3]);
            uint32_t pa2 = pack_h2(s_acc[2 * s + 1][0], s_acc[2 * s + 1][1]);
            uint32_t pa3 = pack_h2(s_acc[2 * s + 1][2], s_acc[2 * s + 1][3]);
#pragma unroll
            for (int nf = 0; nf < 8; nf++) {
                const uint32_t* vp = (const uint32_t*)(st + 128 * ROWB + (nf * 8 + g) * ROWB) + s * 8 + tig;
                mma_f16(o_acc[nf], pa0, pa1, pa2, pa3, vp[0], vp[4]);
            }
        }

        if (kb + 1 < NT) {
            char* nst = fsm + ST_OFF + ((kb + 1) & 1) * ST_SZ;
            uint4* kh = (uint4*)(nst + keyK * ROWB + d0K * 2);
            uint4* kl = (uint4*)(nst + 64 * ROWB + keyK * ROWB + d0K * 2);
            kh[0] = kh0; kh[1] = kh1;
            kl[0] = kl0; kl[1] = kl1;
            char* vt = nst + 128 * ROWB;
            const __half* vh = (const __half*)&vv0;
#pragma unroll
            for (int j = 0; j < 8; j++)
                *(__half*)(vt + (d0V + j) * ROWB + keyV * 2) = vh[j];
            vh = (const __half*)&vv1;
#pragma unroll
            for (int j = 0; j < 8; j++)
                *(__half*)(vt + (d0V + 8 + j) * ROWB + keyV * 2) = vh[j];
        }
        __syncthreads();
    }

    const float inv0 = 1.0f / l0s;
    const float inv1 = 1.0f / l1s;
#pragma unroll
    for (int nf = 0; nf < 8; nf++) {
        const int col = col0 + nf * 8 + tig * 2;
        uint32_t hp, lp;
        split2x(o_acc[nf][0] * inv0, o_acc[nf][1] * inv0, hp, lp);
        *(uint32_t*)(g_Oh + (qrow0 + rowA) * D_MODEL + col) = hp;
        *(uint32_t*)(g_Ol + (qrow0 + rowA) * D_MODEL + col) = lp;
        split2x(o_acc[nf][2] * inv1, o_acc[nf][3] * inv1, hp, lp);
        *(uint32_t*)(g_Oh + (qrow0 + rowA + 8) * D_MODEL + col) = hp;
        *(uint32_t*)(g_Ol + (qrow0 + rowA + 8) * D_MODEL + col) = lp;
    }
}

// ---------------- host launch ----------------
extern "C" void kernel_launch(void* const* d_in, const int* in_sizes, int n_in,
                              void* d_out, int out_size)
{
    const float* query = (const float*)d_in[0];
    const float* key   = (const float*)d_in[1];
    const float* value = (const float*)d_in[2];
    const float* w_q   = (const float*)d_in[3];
    const float* w_k   = (const float*)d_in[4];
    const float* w_v   = (const float*)d_in[5];
    const float* w_o   = (const float*)d_in[6];
    float* out = (float*)d_out;

    cudaFuncSetAttribute(flash_h4_kernel,
                         cudaFuncAttributeMaxDynamicSharedMemorySize, FLASH_SMEM);
    cudaFuncSetAttribute(gemm_h2_kernel,
                         cudaFuncAttributeMaxDynamicSharedMemorySize, GEMM_SMEM);

    zero_sums_kernel<<<1, 32>>>();
    abssum_kernel<<<dim3(128, 4), 256>>>(w_q, w_k, w_v, w_o);
    ternarize_kernel<<<dim3(D_MODEL * D_MODEL / 256, 4), 256>>>(w_q, w_k, w_v, w_o);

    presplit_kernel<<<dim3(PLN / 1024, 3), 256>>>(query, key, value);

    gemm_h2_kernel<<<dim3(D_MODEL / GBN, MROWS / GBM, 3), 256, GEMM_SMEM>>>(nullptr, 0);

    flash_h4_kernel<<<dim3(SEQ / FQT, NHEADS, BATCH), 256, FLASH_SMEM>>>();

    gemm_h2_kernel<<<dim3(D_MODEL / GBN, MROWS / GBM, 1), 256, GEMM_SMEM>>>(out, 1);
}

// round 13
// speedup vs baseline: 1.3411x; 1.0015x over previous
#include <cuda_runtime.h>
#include <cuda_fp16.h>
#include <math.h>
#include <stdint.h>

#define D_MODEL 1024
#define NHEADS  16
#define HDIM    64
#define BATCH   2
#define SEQ     2048
#define MROWS   (BATCH*SEQ)   // 4096
#define PLN     (MROWS*D_MODEL)

// ---------------- device scratch ----------------
__device__ __align__(128) float g_sums[4];
__device__ __align__(128) __half g_Wh[4][D_MODEL*D_MODEL];
__device__ __align__(128) __half g_Xh[3][PLN];
__device__ __align__(128) __half g_Xl[3][PLN];
__device__ __align__(128) __half g_Qh[PLN];   // pre-scaled by 0.125*log2(e)
__device__ __align__(128) __half g_Ql[PLN];
__device__ __align__(128) __half g_Kh[PLN];
__device__ __align__(128) __half g_Kl[PLN];
__device__ __align__(128) __half g_Vh[PLN];
__device__ __align__(128) __half g_Oh[PLN];
__device__ __align__(128) __half g_Ol[PLN];

#define QSCALE 0.18033688011112042f   // 0.125 * log2(e)

// ---------------- helpers ----------------
__device__ __forceinline__ void mma_f16(float* c,
    uint32_t a0, uint32_t a1, uint32_t a2, uint32_t a3,
    uint32_t b0, uint32_t b1)
{
    asm volatile(
        "mma.sync.aligned.m16n8k16.row.col.f32.f16.f16.f32 "
        "{%0,%1,%2,%3}, {%4,%5,%6,%7}, {%8,%9}, {%0,%1,%2,%3};"
        : "+f"(c[0]), "+f"(c[1]), "+f"(c[2]), "+f"(c[3])
        : "r"(a0), "r"(a1), "r"(a2), "r"(a3), "r"(b0), "r"(b1));
}

__device__ __forceinline__ void split2x(float x, float y, uint32_t& hp, uint32_t& lp) {
    __half hx = __float2half_rn(x);
    __half hy = __float2half_rn(y);
    __half lx = __float2half_rn(x - __half2float(hx));
    __half ly = __float2half_rn(y - __half2float(hy));
    __half2 h2 = __halves2half2(hx, hy);
    __half2 l2 = __halves2half2(lx, ly);
    hp = *reinterpret_cast<uint32_t*>(&h2);
    lp = *reinterpret_cast<uint32_t*>(&l2);
}
__device__ __forceinline__ uint32_t pack_h2(float x, float y) {
    __half2 t = __floats2half2_rn(x, y);
    return *reinterpret_cast<uint32_t*>(&t);
}

// ---------------- ternarize ----------------
__global__ void zero_sums_kernel() {
    if (threadIdx.x < 4) g_sums[threadIdx.x] = 0.0f;
}

__global__ __launch_bounds__(256) void abssum_kernel(
    const float* __restrict__ w0, const float* __restrict__ w1,
    const float* __restrict__ w2, const float* __restrict__ w3)
{
    const float* w = (blockIdx.y == 0) ? w0 : (blockIdx.y == 1) ? w1
                     : (blockIdx.y == 2) ? w2 : w3;
    const int n = D_MODEL * D_MODEL;
    float s = 0.0f;
    for (int i = blockIdx.x * blockDim.x + threadIdx.x; i < n;
         i += gridDim.x * blockDim.x)
        s += fabsf(w[i]);
    __shared__ float red[256];
    red[threadIdx.x] = s;
    __syncthreads();
    for (int o = 128; o > 0; o >>= 1) {
        if (threadIdx.x < o) red[threadIdx.x] += red[threadIdx.x + o];
        __syncthreads();
    }
    if (threadIdx.x == 0) atomicAdd(&g_sums[blockIdx.y], red[0]);
}

__global__ __launch_bounds__(256) void ternarize_kernel(
    const float* __restrict__ w0, const float* __restrict__ w1,
    const float* __restrict__ w2, const float* __restrict__ w3)
{
    const int m = blockIdx.y;
    const float* w = (m == 0) ? w0 : (m == 1) ? w1 : (m == 2) ? w2 : w3;
    const float mean = g_sums[m] * (1.0f / (float)(D_MODEL * D_MODEL));
    int i = blockIdx.x * blockDim.x + threadIdx.x;
    float v = w[i];
    float t = (fabsf(v) > mean) ? (v > 0.0f ? 1.0f : -1.0f) : 0.0f;
    g_Wh[m][i] = __float2half_rn(t);
}

// ---------------- pre-split inputs ----------------
__global__ __launch_bounds__(256) void presplit_kernel(
    const float* __restrict__ q, const float* __restrict__ k,
    const float* __restrict__ v)
{
    const int z = blockIdx.y;
    const float* src = (z == 0) ? q : (z == 1) ? k : v;
    __half* hP = g_Xh[z];
    __half* lP = g_Xl[z];
    const int i = (blockIdx.x * blockDim.x + threadIdx.x) * 4;
    float4 val = *(const float4*)(src + i);
    uint32_t h0, l0, h1, l1;
    split2x(val.x, val.y, h0, l0);
    split2x(val.z, val.w, h1, l1);
    *(uint32_t*)(hP + i)     = h0;
    *(uint32_t*)(hP + i + 2) = h1;
    *(uint32_t*)(lP + i)     = l0;
    *(uint32_t*)(lP + i + 2) = l1;
}

// ---------------- GEMM: double-buffered, one sync per chunk ----------------
#define GBM 128
#define GBN 128
#define GBK 32
#define SRH 40
#define NCH (D_MODEL/GBK)
#define GPL (GBM*SRH*2)        // 10240
#define GST (3*GPL)            // 30720
#define GEMM_SMEM (2*GST)      // 61440

__global__ __launch_bounds__(256, 2) void gemm_h2_kernel(float* __restrict__ outF, int which)
{
    extern __shared__ char gsm[];

    const int tid  = threadIdx.x;
    const int lane = tid & 31;
    const int wid  = tid >> 5;
    const int wm   = wid & 1;
    const int wn   = wid >> 1;
    const int g    = lane >> 2;
    const int tig  = lane & 3;

    const int z  = blockIdx.z;
    const __half *Ah_, *Al_, *W_;
    if (which == 0) {
        Ah_ = g_Xh[z]; Al_ = g_Xl[z]; W_ = g_Wh[z];
    } else {
        Ah_ = g_Oh; Al_ = g_Ol; W_ = g_Wh[3];
    }

    const int bm = blockIdx.y * GBM;
    const int bn = blockIdx.x * GBN;

    const int lr = tid >> 1;
    const int lk = (tid & 1) * 16;
    const __half* AhP = Ah_ + (size_t)(bm + lr) * D_MODEL + lk;
    const __half* AlP = Al_ + (size_t)(bm + lr) * D_MODEL + lk;
    const __half* WP  = W_  + (size_t)(bn + lr) * D_MODEL + lk;
    const int soff = lr * (SRH * 2) + lk * 2;

    float acc[4][4][4];
#pragma unroll
    for (int mf = 0; mf < 4; mf++)
#pragma unroll
        for (int nf = 0; nf < 4; nf++)
#pragma unroll
            for (int r = 0; r < 4; r++) acc[mf][nf][r] = 0.0f;

    uint4 pah0 = *(const uint4*)(AhP);
    uint4 pah1 = *(const uint4*)(AhP + 8);
    uint4 pal0 = *(const uint4*)(AlP);
    uint4 pal1 = *(const uint4*)(AlP + 8);
    uint4 pb0  = *(const uint4*)(WP);
    uint4 pb1  = *(const uint4*)(WP + 8);
    {
        uint4* dh = (uint4*)(gsm + 0 * GST + 0 * GPL + soff);
        uint4* dl = (uint4*)(gsm + 0 * GST + 1 * GPL + soff);
        uint4* db = (uint4*)(gsm + 0 * GST + 2 * GPL + soff);
        dh[0] = pah0; dh[1] = pah1;
        dl[0] = pal0; dl[1] = pal1;
        db[0] = pb0;  db[1] = pb1;
    }
    __syncthreads();

    for (int c = 0; c < NCH; c++) {
        const char* st = gsm + (c & 1) * GST;

        if (c + 1 < NCH) {
            const int ko = (c + 1) * GBK;
            pah0 = *(const uint4*)(AhP + ko);
            pah1 = *(const uint4*)(AhP + ko + 8);
            pal0 = *(const uint4*)(AlP + ko);
            pal1 = *(const uint4*)(AlP + ko + 8);
            pb0  = *(const uint4*)(WP + ko);
            pb1  = *(const uint4*)(WP + ko + 8);
        }

#pragma unroll
        for (int s = 0; s < 2; s++) {
            uint32_t bf[4][2];
#pragma unroll
            for (int nf = 0; nf < 4; nf++) {
                const int n = wn * 32 + nf * 8 + g;
                const uint32_t* bp = (const uint32_t*)(st + 2 * GPL + n * SRH * 2) + s * 8 + tig;
                bf[nf][0] = bp[0];
                bf[nf][1] = bp[4];
            }
#pragma unroll
            for (int mf = 0; mf < 4; mf++) {
                const int m = wm * 64 + mf * 16;
                const uint32_t* ah0p = (const uint32_t*)(st + 0 * GPL + (m + g) * SRH * 2) + s * 8 + tig;
                const uint32_t* ah1p = (const uint32_t*)(st + 0 * GPL + (m + g + 8) * SRH * 2) + s * 8 + tig;
                const uint32_t* al0p = (const uint32_t*)(st + 1 * GPL + (m + g) * SRH * 2) + s * 8 + tig;
                const uint32_t* al1p = (const uint32_t*)(st + 1 * GPL + (m + g + 8) * SRH * 2) + s * 8 + tig;
                uint32_t h0 = ah0p[0], h2 = ah0p[4];
                uint32_t h1 = ah1p[0], h3 = ah1p[4];
                uint32_t l0 = al0p[0], l2 = al0p[4];
                uint32_t l1 = al1p[0], l3 = al1p[4];
#pragma unroll
                for (int nf = 0; nf < 4; nf++) {
                    mma_f16(acc[mf][nf], l0, l1, l2, l3, bf[nf][0], bf[nf][1]);
                    mma_f16(acc[mf][nf], h0, h1, h2, h3, bf[nf][0], bf[nf][1]);
                }
            }
        }

        if (c + 1 < NCH) {
            char* nst = gsm + ((c + 1) & 1) * GST;
            uint4* dh = (uint4*)(nst + 0 * GPL + soff);
            uint4* dl = (uint4*)(nst + 1 * GPL + soff);
            uint4* db = (uint4*)(nst + 2 * GPL + soff);
            dh[0] = pah0; dh[1] = pah1;
            dl[0] = pal0; dl[1] = pal1;
            db[0] = pb0;  db[1] = pb1;
        }
        __syncthreads();
    }

    const int mode = (which == 1) ? 2 : (z == 2) ? 1 : 0;
    const float scale = (which == 0 && z == 0) ? QSCALE : 1.0f;
    __half* oh = nullptr;
    __half* ol = nullptr;
    if (which == 0) {
        if (z == 0)      { oh = g_Qh; ol = g_Ql; }
        else if (z == 1) { oh = g_Kh; ol = g_Kl; }
        else             { oh = g_Vh; }
    }

#pragma unroll
    for (int mf = 0; mf < 4; mf++) {
        const int row = bm + wm * 64 + mf * 16 + g;
#pragma unroll
        for (int nf = 0; nf < 4; nf++) {
            const int col = bn + wn * 32 + nf * 8 + tig * 2;
            if (mode == 2) {
                *(float2*)&outF[(size_t)row * D_MODEL + col] =
                    make_float2(acc[mf][nf][0], acc[mf][nf][1]);
                *(float2*)&outF[(size_t)(row + 8) * D_MODEL + col] =
                    make_float2(acc[mf][nf][2], acc[mf][nf][3]);
            } else if (mode == 0) {
                uint32_t hp, lp;
                split2x(acc[mf][nf][0] * scale, acc[mf][nf][1] * scale, hp, lp);
                *(uint32_t*)(oh + (size_t)row * D_MODEL + col) = hp;
                *(uint32_t*)(ol + (size_t)row * D_MODEL + col) = lp;
                split2x(acc[mf][nf][2] * scale, acc[mf][nf][3] * scale, hp, lp);
                *(uint32_t*)(oh + (size_t)(row + 8) * D_MODEL + col) = hp;
                *(uint32_t*)(ol + (size_t)(row + 8) * D_MODEL + col) = lp;
            } else {
                __half2 v0 = __floats2half2_rn(acc[mf][nf][0], acc[mf][nf][1]);
                __half2 v1 = __floats2half2_rn(acc[mf][nf][2], acc[mf][nf][3]);
                *(uint32_t*)(oh + (size_t)row * D_MODEL + col) = *(uint32_t*)&v0;
                *(uint32_t*)(oh + (size_t)(row + 8) * D_MODEL + col) = *(uint32_t*)&v1;
            }
        }
    }
}

// ---------------- flash: 4 warps x 32 q-rows (2 m-tiles/warp), K-frag reuse ----------------
#define FQT 128
#define FKT 64
#define NT  (SEQ/FKT)
#define ROWB 144
#define QH_OFF 0
#define QL_OFF (128*ROWB)
#define ST_OFF (2*128*ROWB)      // 36864
#define ST_SZ  (3*64*ROWB)       // 27648
#define FLASH_SMEM (ST_OFF + 2*ST_SZ)   // 92160 -> 2 blocks/SM

__global__ __launch_bounds__(128, 2) void flash_h5_kernel()
{
    extern __shared__ char fsm[];

    const int tid  = threadIdx.x;      // 0..127
    const int lane = tid & 31;
    const int wid  = tid >> 5;         // 0..3
    const int g    = lane >> 2;
    const int tig  = lane & 3;

    const int qb = blockIdx.x;
    const int h  = blockIdx.y;
    const int b  = blockIdx.z;
    const size_t qrow0 = (size_t)b * SEQ + (size_t)qb * FQT;
    const int col0 = h * HDIM;

    // ---- load Q tile planes (one row per thread) ----
    {
        const __half* sh = g_Qh + (qrow0 + tid) * D_MODEL + col0;
        const __half* sl = g_Ql + (qrow0 + tid) * D_MODEL + col0;
        uint4* dh = (uint4*)(fsm + QH_OFF + tid * ROWB);
        uint4* dl = (uint4*)(fsm + QL_OFF + tid * ROWB);
#pragma unroll
        for (int p = 0; p < 8; p++) {
            dh[p] = *(const uint4*)(sh + 8 * p);
            dl[p] = *(const uint4*)(sl + 8 * p);
        }
    }

    const int wb = wid * 32;           // warp's 32-row slab

    // loader roles (128 threads)
    const int keyK = tid >> 1;         // 0..63
    const int d0K  = (tid & 1) * 32;   // halves
    const int keyV = tid & 63;
    const int d0V  = (tid >> 6) * 32;  // dims
    const size_t kvbase = (size_t)b * SEQ * D_MODEL + col0;

    float o_acc[2][8][4];
#pragma unroll
    for (int mf = 0; mf < 2; mf++)
#pragma unroll
        for (int nf = 0; nf < 8; nf++)
#pragma unroll
            for (int r = 0; r < 4; r++) o_acc[mf][nf][r] = 0.0f;
    float m_[2][2], l_[2][2];
#pragma unroll
    for (int mf = 0; mf < 2; mf++) {
        m_[mf][0] = -INFINITY; m_[mf][1] = -INFINITY;
        l_[mf][0] = 0.0f;      l_[mf][1] = 0.0f;
    }

    // ---- prefetch tile 0 ----
    uint4 kh[4], kl[4], vv[4];
    {
        const size_t sk = kvbase + (size_t)keyK * D_MODEL + d0K;
#pragma unroll
        for (int j = 0; j < 4; j++) {
            kh[j] = *(const uint4*)(g_Kh + sk + 8 * j);
            kl[j] = *(const uint4*)(g_Kl + sk + 8 * j);
        }
        const size_t sv = kvbase + (size_t)keyV * D_MODEL + d0V;
#pragma unroll
        for (int j = 0; j < 4; j++)
            vv[j] = *(const uint4*)(g_Vh + sv + 8 * j);
    }
    {
        char* st = fsm + ST_OFF;
        uint4* khp = (uint4*)(st + keyK * ROWB + d0K * 2);
        uint4* klp = (uint4*)(st + 64 * ROWB + keyK * ROWB + d0K * 2);
#pragma unroll
        for (int j = 0; j < 4; j++) { khp[j] = kh[j]; klp[j] = kl[j]; }
        char* vt = st + 128 * ROWB;
#pragma unroll
        for (int q = 0; q < 4; q++) {
            const __half* vh = (const __half*)&vv[q];
#pragma unroll
            for (int j = 0; j < 8; j++)
                *(__half*)(vt + (d0V + 8 * q + j) * ROWB + keyV * 2) = vh[j];
        }
    }
    __syncthreads();

    for (int kb = 0; kb < NT; kb++) {
        const char* st = fsm + ST_OFF + (kb & 1) * ST_SZ;

        // ---- prefetch next tile ----
        if (kb + 1 < NT) {
            const size_t sk = kvbase + ((size_t)(kb + 1) * FKT + keyK) * D_MODEL + d0K;
#pragma unroll
            for (int j = 0; j < 4; j++) {
                kh[j] = *(const uint4*)(g_Kh + sk + 8 * j);
                kl[j] = *(const uint4*)(g_Kl + sk + 8 * j);
            }
            const size_t sv = kvbase + ((size_t)(kb + 1) * FKT + keyV) * D_MODEL + d0V;
#pragma unroll
            for (int j = 0; j < 4; j++)
                vv[j] = *(const uint4*)(g_Vh + sv + 8 * j);
        }

        // ---- S = Q @ K^T : 4 k16 steps, 3 fp16 terms, 2 m-tiles share K frags ----
        float s_acc[2][8][4];
#pragma unroll
        for (int mf = 0; mf < 2; mf++)
#pragma unroll
            for (int nf = 0; nf < 8; nf++)
#pragma unroll
                for (int r = 0; r < 4; r++) s_acc[mf][nf][r] = 0.0f;

#pragma unroll
        for (int s = 0; s < 4; s++) {
            uint32_t qa[2][8];
#pragma unroll
            for (int mf = 0; mf < 2; mf++) {
                const int rA = wb + mf * 16 + g;
                const uint32_t* qh0p = (const uint32_t*)(fsm + QH_OFF + rA * ROWB) + s * 8 + tig;
                const uint32_t* qh1p = (const uint32_t*)(fsm + QH_OFF + (rA + 8) * ROWB) + s * 8 + tig;
                const uint32_t* ql0p = (const uint32_t*)(fsm + QL_OFF + rA * ROWB) + s * 8 + tig;
                const uint32_t* ql1p = (const uint32_t*)(fsm + QL_OFF + (rA + 8) * ROWB) + s * 8 + tig;
                qa[mf][0] = qh0p[0]; qa[mf][2] = qh0p[4];
                qa[mf][1] = qh1p[0]; qa[mf][3] = qh1p[4];
                qa[mf][4] = ql0p[0]; qa[mf][6] = ql0p[4];
                qa[mf][5] = ql1p[0]; qa[mf][7] = ql1p[4];
            }
#pragma unroll
            for (int nf = 0; nf < 8; nf++) {
                const uint32_t* khp = (const uint32_t*)(st + (nf * 8 + g) * ROWB) + s * 8 + tig;
                const uint32_t* klp = (const uint32_t*)(st + 64 * ROWB + (nf * 8 + g) * ROWB) + s * 8 + tig;
                uint32_t bh0 = khp[0], bh1 = khp[4];
                uint32_t bl0 = klp[0], bl1 = klp[4];
#pragma unroll
                for (int mf = 0; mf < 2; mf++) {
                    mma_f16(s_acc[mf][nf], qa[mf][0], qa[mf][1], qa[mf][2], qa[mf][3], bh0, bh1);
                    mma_f16(s_acc[mf][nf], qa[mf][4], qa[mf][5], qa[mf][6], qa[mf][7], bh0, bh1);
                    mma_f16(s_acc[mf][nf], qa[mf][0], qa[mf][1], qa[mf][2], qa[mf][3], bl0, bl1);
                }
            }
        }

        // ---- online softmax (log2 domain), per m-tile ----
#pragma unroll
        for (int mf = 0; mf < 2; mf++) {
            float mx0 = m_[mf][0], mx1 = m_[mf][1];
#pragma unroll
            for (int nf = 0; nf < 8; nf++) {
                mx0 = fmaxf(mx0, fmaxf(s_acc[mf][nf][0], s_acc[mf][nf][1]));
                mx1 = fmaxf(mx1, fmaxf(s_acc[mf][nf][2], s_acc[mf][nf][3]));
            }
            mx0 = fmaxf(mx0, __shfl_xor_sync(0xffffffff, mx0, 1));
            mx0 = fmaxf(mx0, __shfl_xor_sync(0xffffffff, mx0, 2));
            mx1 = fmaxf(mx1, __shfl_xor_sync(0xffffffff, mx1, 1));
            mx1 = fmaxf(mx1, __shfl_xor_sync(0xffffffff, mx1, 2));
            float sc0 = exp2f(m_[mf][0] - mx0);
            float sc1 = exp2f(m_[mf][1] - mx1);
            m_[mf][0] = mx0; m_[mf][1] = mx1;
            float sum0 = 0.0f, sum1 = 0.0f;
#pragma unroll
            for (int nf = 0; nf < 8; nf++) {
                s_acc[mf][nf][0] = exp2f(s_acc[mf][nf][0] - mx0);
                s_acc[mf][nf][1] = exp2f(s_acc[mf][nf][1] - mx0);
                s_acc[mf][nf][2] = exp2f(s_acc[mf][nf][2] - mx1);
                s_acc[mf][nf][3] = exp2f(s_acc[mf][nf][3] - mx1);
                sum0 += s_acc[mf][nf][0] + s_acc[mf][nf][1];
                sum1 += s_acc[mf][nf][2] + s_acc[mf][nf][3];
            }
            sum0 += __shfl_xor_sync(0xffffffff, sum0, 1);
            sum0 += __shfl_xor_sync(0xffffffff, sum0, 2);
            sum1 += __shfl_xor_sync(0xffffffff, sum1, 1);
            sum1 += __shfl_xor_sync(0xffffffff, sum1, 2);
            l_[mf][0] = l_[mf][0] * sc0 + sum0;
            l_[mf][1] = l_[mf][1] * sc1 + sum1;
#pragma unroll
            for (int nf = 0; nf < 8; nf++) {
                o_acc[mf][nf][0] *= sc0; o_acc[mf][nf][1] *= sc0;
                o_acc[mf][nf][2] *= sc1; o_acc[mf][nf][3] *= sc1;
            }
        }

        // ---- O += P @ V : register repack, V frags shared across m-tiles ----
#pragma unroll
        for (int s = 0; s < 4; s++) {
            uint32_t pa[2][4];
#pragma unroll
            for (int mf = 0; mf < 2; mf++) {
                pa[mf][0] = pack_h2(s_acc[mf][2 * s][0],     s_acc[mf][2 * s][1]);
                pa[mf][1] = pack_h2(s_acc[mf][2 * s][2],     s_acc[mf][2 * s][3]);
                pa[mf][2] = pack_h2(s_acc[mf][2 * s + 1][0], s_acc[mf][2 * s + 1][1]);
                pa[mf][3] = pack_h2(s_acc[mf][2 * s + 1][2], s_acc[mf][2 * s + 1][3]);
            }
#pragma unroll
            for (int nf = 0; nf < 8; nf++) {
                const uint32_t* vp = (const uint32_t*)(st + 128 * ROWB + (nf * 8 + g) * ROWB) + s * 8 + tig;
                uint32_t b0 = vp[0], b1 = vp[4];
#pragma unroll
                for (int mf = 0; mf < 2; mf++)
                    mma_f16(o_acc[mf][nf], pa[mf][0], pa[mf][1], pa[mf][2], pa[mf][3], b0, b1);
            }
        }

        // ---- store prefetched tile to the other stage ----
        if (kb + 1 < NT) {
            char* nst = fsm + ST_OFF + ((kb + 1) & 1) * ST_SZ;
            uint4* khp = (uint4*)(nst + keyK * ROWB + d0K * 2);
            uint4* klp = (uint4*)(nst + 64 * ROWB + keyK * ROWB + d0K * 2);
#pragma unroll
            for (int j = 0; j < 4; j++) { khp[j] = kh[j]; klp[j] = kl[j]; }
            char* vt = nst + 128 * ROWB;
#pragma unroll
            for (int q = 0; q < 4; q++) {
                const __half* vh = (const __half*)&vv[q];
#pragma unroll
                for (int j = 0; j < 8; j++)
                    *(__half*)(vt + (d0V + 8 * q + j) * ROWB + keyV * 2) = vh[j];
            }
        }
        __syncthreads();
    }

    // ---- finalize: write O as h/l fp16 planes ----
#pragma unroll
    for (int mf = 0; mf < 2; mf++) {
        const int rA = wb + mf * 16 + g;
        const float inv0 = 1.0f / l_[mf][0];
        const float inv1 = 1.0f / l_[mf][1];
#pragma unroll
        for (int nf = 0; nf < 8; nf++) {
            const int col = col0 + nf * 8 + tig * 2;
            uint32_t hp, lp;
            split2x(o_acc[mf][nf][0] * inv0, o_acc[mf][nf][1] * inv0, hp, lp);
            *(uint32_t*)(g_Oh + (qrow0 + rA) * D_MODEL + col) = hp;
            *(uint32_t*)(g_Ol + (qrow0 + rA) * D_MODEL + col) = lp;
            split2x(o_acc[mf][nf][2] * inv1, o_acc[mf][nf][3] * inv1, hp, lp);
            *(uint32_t*)(g_Oh + (qrow0 + rA + 8) * D_MODEL + col) = hp;
            *(uint32_t*)(g_Ol + (qrow0 + rA + 8) * D_MODEL + col) = lp;
        }
    }
}

// ---------------- host launch ----------------
extern "C" void kernel_launch(void* const* d_in, const int* in_sizes, int n_in,
                              void* d_out, int out_size)
{
    const float* query = (const float*)d_in[0];
    const float* key   = (const float*)d_in[1];
    const float* value = (const float*)d_in[2];
    const float* w_q   = (const float*)d_in[3];
    const float* w_k   = (const float*)d_in[4];
    const float* w_v   = (const float*)d_in[5];
    const float* w_o   = (const float*)d_in[6];
    float* out = (float*)d_out;

    cudaFuncSetAttribute(flash_h5_kernel,
                         cudaFuncAttributeMaxDynamicSharedMemorySize, FLASH_SMEM);
    cudaFuncSetAttribute(gemm_h2_kernel,
                         cudaFuncAttributeMaxDynamicSharedMemorySize, GEMM_SMEM);

    zero_sums_kernel<<<1, 32>>>();
    abssum_kernel<<<dim3(128, 4), 256>>>(w_q, w_k, w_v, w_o);
    ternarize_kernel<<<dim3(D_MODEL * D_MODEL / 256, 4), 256>>>(w_q, w_k, w_v, w_o);

    presplit_kernel<<<dim3(PLN / 1024, 3), 256>>>(query, key, value);

    gemm_h2_kernel<<<dim3(D_MODEL / GBN, MROWS / GBM, 3), 256, GEMM_SMEM>>>(nullptr, 0);

    flash_h5_kernel<<<dim3(SEQ / FQT, NHEADS, BATCH), 128, FLASH_SMEM>>>();

    gemm_h2_kernel<<<dim3(D_MODEL / GBN, MROWS / GBM, 1), 256, GEMM_SMEM>>>(out, 1);
}

// round 14
// speedup vs baseline: 1.4870x; 1.1088x over previous
#include <cuda_runtime.h>
#include <cuda_fp16.h>
#include <math.h>
#include <stdint.h>

#define D_MODEL 1024
#define NHEADS  16
#define HDIM    64
#define BATCH   2
#define SEQ     2048
#define MROWS   (BATCH*SEQ)   // 4096
#define PLN     (MROWS*D_MODEL)

// ---------------- device scratch ----------------
__device__ __align__(128) float g_sums[4];
__device__ __align__(128) __half g_Wh[4][D_MODEL*D_MODEL];
__device__ __align__(128) __half g_Xh[3][PLN];
__device__ __align__(128) __half g_Xl[3][PLN];   // lo planes (z=2 unused)
__device__ __align__(128) __half g_Qh[PLN];      // pre-scaled by 0.125*log2(e)
__device__ __align__(128) __half g_Ql[PLN];
__device__ __align__(128) __half g_Kh[PLN];
__device__ __align__(128) __half g_Kl[PLN];
__device__ __align__(128) __half g_Vh[PLN];
__device__ __align__(128) __half g_Oh[PLN];      // attention out, single fp16

#define QSCALE 0.18033688011112042f   // 0.125 * log2(e)

// ---------------- helpers ----------------
__device__ __forceinline__ void mma_f16(float* c,
    uint32_t a0, uint32_t a1, uint32_t a2, uint32_t a3,
    uint32_t b0, uint32_t b1)
{
    asm volatile(
        "mma.sync.aligned.m16n8k16.row.col.f32.f16.f16.f32 "
        "{%0,%1,%2,%3}, {%4,%5,%6,%7}, {%8,%9}, {%0,%1,%2,%3};"
        : "+f"(c[0]), "+f"(c[1]), "+f"(c[2]), "+f"(c[3])
        : "r"(a0), "r"(a1), "r"(a2), "r"(a3), "r"(b0), "r"(b1));
}

__device__ __forceinline__ void split2x(float x, float y, uint32_t& hp, uint32_t& lp) {
    __half hx = __float2half_rn(x);
    __half hy = __float2half_rn(y);
    __half lx = __float2half_rn(x - __half2float(hx));
    __half ly = __float2half_rn(y - __half2float(hy));
    __half2 h2 = __halves2half2(hx, hy);
    __half2 l2 = __halves2half2(lx, ly);
    hp = *reinterpret_cast<uint32_t*>(&h2);
    lp = *reinterpret_cast<uint32_t*>(&l2);
}
__device__ __forceinline__ uint32_t pack_h2(float x, float y) {
    __half2 t = __floats2half2_rn(x, y);
    return *reinterpret_cast<uint32_t*>(&t);
}

// ---------------- ternarize ----------------
__global__ void zero_sums_kernel() {
    if (threadIdx.x < 4) g_sums[threadIdx.x] = 0.0f;
}

__global__ __launch_bounds__(256) void abssum_kernel(
    const float* __restrict__ w0, const float* __restrict__ w1,
    const float* __restrict__ w2, const float* __restrict__ w3)
{
    const float* w = (blockIdx.y == 0) ? w0 : (blockIdx.y == 1) ? w1
                     : (blockIdx.y == 2) ? w2 : w3;
    const int n = D_MODEL * D_MODEL;
    float s = 0.0f;
    for (int i = blockIdx.x * blockDim.x + threadIdx.x; i < n;
         i += gridDim.x * blockDim.x)
        s += fabsf(w[i]);
    __shared__ float red[256];
    red[threadIdx.x] = s;
    __syncthreads();
    for (int o = 128; o > 0; o >>= 1) {
        if (threadIdx.x < o) red[threadIdx.x] += red[threadIdx.x + o];
        __syncthreads();
    }
    if (threadIdx.x == 0) atomicAdd(&g_sums[blockIdx.y], red[0]);
}

__global__ __launch_bounds__(256) void ternarize_kernel(
    const float* __restrict__ w0, const float* __restrict__ w1,
    const float* __restrict__ w2, const float* __restrict__ w3)
{
    const int m = blockIdx.y;
    const float* w = (m == 0) ? w0 : (m == 1) ? w1 : (m == 2) ? w2 : w3;
    const float mean = g_sums[m] * (1.0f / (float)(D_MODEL * D_MODEL));
    int i = blockIdx.x * blockDim.x + threadIdx.x;
    float v = w[i];
    float t = (fabsf(v) > mean) ? (v > 0.0f ? 1.0f : -1.0f) : 0.0f;
    g_Wh[m][i] = __float2half_rn(t);
}

// ---------------- pre-split inputs (V: hi plane only) ----------------
__global__ __launch_bounds__(256) void presplit_kernel(
    const float* __restrict__ q, const float* __restrict__ k,
    const float* __restrict__ v)
{
    const int z = blockIdx.y;
    const float* src = (z == 0) ? q : (z == 1) ? k : v;
    __half* hP = g_Xh[z];
    __half* lP = g_Xl[z];
    const int i = (blockIdx.x * blockDim.x + threadIdx.x) * 4;
    float4 val = *(const float4*)(src + i);
    uint32_t h0, l0, h1, l1;
    split2x(val.x, val.y, h0, l0);
    split2x(val.z, val.w, h1, l1);
    *(uint32_t*)(hP + i)     = h0;
    *(uint32_t*)(hP + i + 2) = h1;
    if (z < 2) {
        *(uint32_t*)(lP + i)     = l0;
        *(uint32_t*)(lP + i + 2) = l1;
    }
}

// ---------------- GEMM: double-buffered, 1-or-2-term A ----------------
#define GBM 128
#define GBN 128
#define GBK 32
#define SRH 40
#define NCH (D_MODEL/GBK)
#define GPL (GBM*SRH*2)        // 10240
#define GST (3*GPL)            // 30720
#define GEMM_SMEM (2*GST)      // 61440

__global__ __launch_bounds__(256, 2) void gemm_h2_kernel(float* __restrict__ outF, int which)
{
    extern __shared__ char gsm[];

    const int tid  = threadIdx.x;
    const int lane = tid & 31;
    const int wid  = tid >> 5;
    const int wm   = wid & 1;
    const int wn   = wid >> 1;
    const int g    = lane >> 2;
    const int tig  = lane & 3;

    const int z  = blockIdx.z;
    const __half *Ah_, *Al_, *W_;
    if (which == 0) {
        Ah_ = g_Xh[z]; Al_ = g_Xl[z]; W_ = g_Wh[z];
    } else {
        Ah_ = g_Oh; Al_ = g_Oh; W_ = g_Wh[3];
    }
    const int terms = (which == 1 || z == 2) ? 1 : 2;

    const int bm = blockIdx.y * GBM;
    const int bn = blockIdx.x * GBN;

    const int lr = tid >> 1;
    const int lk = (tid & 1) * 16;
    const __half* AhP = Ah_ + (size_t)(bm + lr) * D_MODEL + lk;
    const __half* AlP = Al_ + (size_t)(bm + lr) * D_MODEL + lk;
    const __half* WP  = W_  + (size_t)(bn + lr) * D_MODEL + lk;
    const int soff = lr * (SRH * 2) + lk * 2;

    float acc[4][4][4];
#pragma unroll
    for (int mf = 0; mf < 4; mf++)
#pragma unroll
        for (int nf = 0; nf < 4; nf++)
#pragma unroll
            for (int r = 0; r < 4; r++) acc[mf][nf][r] = 0.0f;

    uint4 pah0 = *(const uint4*)(AhP);
    uint4 pah1 = *(const uint4*)(AhP + 8);
    uint4 pal0, pal1;
    if (terms == 2) {
        pal0 = *(const uint4*)(AlP);
        pal1 = *(const uint4*)(AlP + 8);
    }
    uint4 pb0  = *(const uint4*)(WP);
    uint4 pb1  = *(const uint4*)(WP + 8);
    {
        uint4* dh = (uint4*)(gsm + 0 * GST + 0 * GPL + soff);
        uint4* db = (uint4*)(gsm + 0 * GST + 2 * GPL + soff);
        dh[0] = pah0; dh[1] = pah1;
        db[0] = pb0;  db[1] = pb1;
        if (terms == 2) {
            uint4* dl = (uint4*)(gsm + 0 * GST + 1 * GPL + soff);
            dl[0] = pal0; dl[1] = pal1;
        }
    }
    __syncthreads();

    for (int c = 0; c < NCH; c++) {
        const char* st = gsm + (c & 1) * GST;

        if (c + 1 < NCH) {
            const int ko = (c + 1) * GBK;
            pah0 = *(const uint4*)(AhP + ko);
            pah1 = *(const uint4*)(AhP + ko + 8);
            if (terms == 2) {
                pal0 = *(const uint4*)(AlP + ko);
                pal1 = *(const uint4*)(AlP + ko + 8);
            }
            pb0  = *(const uint4*)(WP + ko);
            pb1  = *(const uint4*)(WP + ko + 8);
        }

#pragma unroll
        for (int s = 0; s < 2; s++) {
            uint32_t bf[4][2];
#pragma unroll
            for (int nf = 0; nf < 4; nf++) {
                const int n = wn * 32 + nf * 8 + g;
                const uint32_t* bp = (const uint32_t*)(st + 2 * GPL + n * SRH * 2) + s * 8 + tig;
                bf[nf][0] = bp[0];
                bf[nf][1] = bp[4];
            }
#pragma unroll
            for (int mf = 0; mf < 4; mf++) {
                const int m = wm * 64 + mf * 16;
                const uint32_t* ah0p = (const uint32_t*)(st + 0 * GPL + (m + g) * SRH * 2) + s * 8 + tig;
                const uint32_t* ah1p = (const uint32_t*)(st + 0 * GPL + (m + g + 8) * SRH * 2) + s * 8 + tig;
                uint32_t h0 = ah0p[0], h2 = ah0p[4];
                uint32_t h1 = ah1p[0], h3 = ah1p[4];
                if (terms == 2) {
                    const uint32_t* al0p = (const uint32_t*)(st + 1 * GPL + (m + g) * SRH * 2) + s * 8 + tig;
                    const uint32_t* al1p = (const uint32_t*)(st + 1 * GPL + (m + g + 8) * SRH * 2) + s * 8 + tig;
                    uint32_t l0 = al0p[0], l2 = al0p[4];
                    uint32_t l1 = al1p[0], l3 = al1p[4];
#pragma unroll
                    for (int nf = 0; nf < 4; nf++)
                        mma_f16(acc[mf][nf], l0, l1, l2, l3, bf[nf][0], bf[nf][1]);
                }
#pragma unroll
                for (int nf = 0; nf < 4; nf++)
                    mma_f16(acc[mf][nf], h0, h1, h2, h3, bf[nf][0], bf[nf][1]);
            }
        }

        if (c + 1 < NCH) {
            char* nst = gsm + ((c + 1) & 1) * GST;
            uint4* dh = (uint4*)(nst + 0 * GPL + soff);
            uint4* db = (uint4*)(nst + 2 * GPL + soff);
            dh[0] = pah0; dh[1] = pah1;
            db[0] = pb0;  db[1] = pb1;
            if (terms == 2) {
                uint4* dl = (uint4*)(nst + 1 * GPL + soff);
                dl[0] = pal0; dl[1] = pal1;
            }
        }
        __syncthreads();
    }

    const int mode = (which == 1) ? 2 : (z == 2) ? 1 : 0;
    const float scale = (which == 0 && z == 0) ? QSCALE : 1.0f;
    __half* oh = nullptr;
    __half* ol = nullptr;
    if (which == 0) {
        if (z == 0)      { oh = g_Qh; ol = g_Ql; }
        else if (z == 1) { oh = g_Kh; ol = g_Kl; }
        else             { oh = g_Vh; }
    }

#pragma unroll
    for (int mf = 0; mf < 4; mf++) {
        const int row = bm + wm * 64 + mf * 16 + g;
#pragma unroll
        for (int nf = 0; nf < 4; nf++) {
            const int col = bn + wn * 32 + nf * 8 + tig * 2;
            if (mode == 2) {
                *(float2*)&outF[(size_t)row * D_MODEL + col] =
                    make_float2(acc[mf][nf][0], acc[mf][nf][1]);
                *(float2*)&outF[(size_t)(row + 8) * D_MODEL + col] =
                    make_float2(acc[mf][nf][2], acc[mf][nf][3]);
            } else if (mode == 0) {
                uint32_t hp, lp;
                split2x(acc[mf][nf][0] * scale, acc[mf][nf][1] * scale, hp, lp);
                *(uint32_t*)(oh + (size_t)row * D_MODEL + col) = hp;
                *(uint32_t*)(ol + (size_t)row * D_MODEL + col) = lp;
                split2x(acc[mf][nf][2] * scale, acc[mf][nf][3] * scale, hp, lp);
                *(uint32_t*)(oh + (size_t)(row + 8) * D_MODEL + col) = hp;
                *(uint32_t*)(ol + (size_t)(row + 8) * D_MODEL + col) = lp;
            } else {
                *(uint32_t*)(oh + (size_t)row * D_MODEL + col) =
                    pack_h2(acc[mf][nf][0], acc[mf][nf][1]);
                *(uint32_t*)(oh + (size_t)(row + 8) * D_MODEL + col) =
                    pack_h2(acc[mf][nf][2], acc[mf][nf][3]);
            }
        }
    }
}

// ---------------- flash: 4 warps x 32 q-rows, single-plane O output ----------------
#define FQT 128
#define FKT 64
#define NT  (SEQ/FKT)
#define ROWB 144
#define QH_OFF 0
#define QL_OFF (128*ROWB)
#define ST_OFF (2*128*ROWB)      // 36864
#define ST_SZ  (3*64*ROWB)       // 27648
#define FLASH_SMEM (ST_OFF + 2*ST_SZ)   // 92160 -> 2 blocks/SM

__global__ __launch_bounds__(128, 2) void flash_h5_kernel()
{
    extern __shared__ char fsm[];

    const int tid  = threadIdx.x;      // 0..127
    const int lane = tid & 31;
    const int wid  = tid >> 5;         // 0..3
    const int g    = lane >> 2;
    const int tig  = lane & 3;

    const int qb = blockIdx.x;
    const int h  = blockIdx.y;
    const int b  = blockIdx.z;
    const size_t qrow0 = (size_t)b * SEQ + (size_t)qb * FQT;
    const int col0 = h * HDIM;

    // ---- load Q tile planes (one row per thread) ----
    {
        const __half* sh = g_Qh + (qrow0 + tid) * D_MODEL + col0;
        const __half* sl = g_Ql + (qrow0 + tid) * D_MODEL + col0;
        uint4* dh = (uint4*)(fsm + QH_OFF + tid * ROWB);
        uint4* dl = (uint4*)(fsm + QL_OFF + tid * ROWB);
#pragma unroll
        for (int p = 0; p < 8; p++) {
            dh[p] = *(const uint4*)(sh + 8 * p);
            dl[p] = *(const uint4*)(sl + 8 * p);
        }
    }

    const int wb = wid * 32;

    const int keyK = tid >> 1;
    const int d0K  = (tid & 1) * 32;
    const int keyV = tid & 63;
    const int d0V  = (tid >> 6) * 32;
    const size_t kvbase = (size_t)b * SEQ * D_MODEL + col0;

    float o_acc[2][8][4];
#pragma unroll
    for (int mf = 0; mf < 2; mf++)
#pragma unroll
        for (int nf = 0; nf < 8; nf++)
#pragma unroll
            for (int r = 0; r < 4; r++) o_acc[mf][nf][r] = 0.0f;
    float m_[2][2], l_[2][2];
#pragma unroll
    for (int mf = 0; mf < 2; mf++) {
        m_[mf][0] = -INFINITY; m_[mf][1] = -INFINITY;
        l_[mf][0] = 0.0f;      l_[mf][1] = 0.0f;
    }

    uint4 kh[4], kl[4], vv[4];
    {
        const size_t sk = kvbase + (size_t)keyK * D_MODEL + d0K;
#pragma unroll
        for (int j = 0; j < 4; j++) {
            kh[j] = *(const uint4*)(g_Kh + sk + 8 * j);
            kl[j] = *(const uint4*)(g_Kl + sk + 8 * j);
        }
        const size_t sv = kvbase + (size_t)keyV * D_MODEL + d0V;
#pragma unroll
        for (int j = 0; j < 4; j++)
            vv[j] = *(const uint4*)(g_Vh + sv + 8 * j);
    }
    {
        char* st = fsm + ST_OFF;
        uint4* khp = (uint4*)(st + keyK * ROWB + d0K * 2);
        uint4* klp = (uint4*)(st + 64 * ROWB + keyK * ROWB + d0K * 2);
#pragma unroll
        for (int j = 0; j < 4; j++) { khp[j] = kh[j]; klp[j] = kl[j]; }
        char* vt = st + 128 * ROWB;
#pragma unroll
        for (int q = 0; q < 4; q++) {
            const __half* vh = (const __half*)&vv[q];
#pragma unroll
            for (int j = 0; j < 8; j++)
                *(__half*)(vt + (d0V + 8 * q + j) * ROWB + keyV * 2) = vh[j];
        }
    }
    __syncthreads();

    for (int kb = 0; kb < NT; kb++) {
        const char* st = fsm + ST_OFF + (kb & 1) * ST_SZ;

        if (kb + 1 < NT) {
            const size_t sk = kvbase + ((size_t)(kb + 1) * FKT + keyK) * D_MODEL + d0K;
#pragma unroll
            for (int j = 0; j < 4; j++) {
                kh[j] = *(const uint4*)(g_Kh + sk + 8 * j);
                kl[j] = *(const uint4*)(g_Kl + sk + 8 * j);
            }
            const size_t sv = kvbase + ((size_t)(kb + 1) * FKT + keyV) * D_MODEL + d0V;
#pragma unroll
            for (int j = 0; j < 4; j++)
                vv[j] = *(const uint4*)(g_Vh + sv + 8 * j);
        }

        float s_acc[2][8][4];
#pragma unroll
        for (int mf = 0; mf < 2; mf++)
#pragma unroll
            for (int nf = 0; nf < 8; nf++)
#pragma unroll
                for (int r = 0; r < 4; r++) s_acc[mf][nf][r] = 0.0f;

#pragma unroll
        for (int s = 0; s < 4; s++) {
            uint32_t qa[2][8];
#pragma unroll
            for (int mf = 0; mf < 2; mf++) {
                const int rA = wb + mf * 16 + g;
                const uint32_t* qh0p = (const uint32_t*)(fsm + QH_OFF + rA * ROWB) + s * 8 + tig;
                const uint32_t* qh1p = (const uint32_t*)(fsm + QH_OFF + (rA + 8) * ROWB) + s * 8 + tig;
                const uint32_t* ql0p = (const uint32_t*)(fsm + QL_OFF + rA * ROWB) + s * 8 + tig;
                const uint32_t* ql1p = (const uint32_t*)(fsm + QL_OFF + (rA + 8) * ROWB) + s * 8 + tig;
                qa[mf][0] = qh0p[0]; qa[mf][2] = qh0p[4];
                qa[mf][1] = qh1p[0]; qa[mf][3] = qh1p[4];
                qa[mf][4] = ql0p[0]; qa[mf][6] = ql0p[4];
                qa[mf][5] = ql1p[0]; qa[mf][7] = ql1p[4];
            }
#pragma unroll
            for (int nf = 0; nf < 8; nf++) {
                const uint32_t* khp = (const uint32_t*)(st + (nf * 8 + g) * ROWB) + s * 8 + tig;
                const uint32_t* klp = (const uint32_t*)(st + 64 * ROWB + (nf * 8 + g) * ROWB) + s * 8 + tig;
                uint32_t bh0 = khp[0], bh1 = khp[4];
                uint32_t bl0 = klp[0], bl1 = klp[4];
#pragma unroll
                for (int mf = 0; mf < 2; mf++) {
                    mma_f16(s_acc[mf][nf], qa[mf][0], qa[mf][1], qa[mf][2], qa[mf][3], bh0, bh1);
                    mma_f16(s_acc[mf][nf], qa[mf][4], qa[mf][5], qa[mf][6], qa[mf][7], bh0, bh1);
                    mma_f16(s_acc[mf][nf], qa[mf][0], qa[mf][1], qa[mf][2], qa[mf][3], bl0, bl1);
                }
            }
        }

#pragma unroll
        for (int mf = 0; mf < 2; mf++) {
            float mx0 = m_[mf][0], mx1 = m_[mf][1];
#pragma unroll
            for (int nf = 0; nf < 8; nf++) {
                mx0 = fmaxf(mx0, fmaxf(s_acc[mf][nf][0], s_acc[mf][nf][1]));
                mx1 = fmaxf(mx1, fmaxf(s_acc[mf][nf][2], s_acc[mf][nf][3]));
            }
            mx0 = fmaxf(mx0, __shfl_xor_sync(0xffffffff, mx0, 1));
            mx0 = fmaxf(mx0, __shfl_xor_sync(0xffffffff, mx0, 2));
            mx1 = fmaxf(mx1, __shfl_xor_sync(0xffffffff, mx1, 1));
            mx1 = fmaxf(mx1, __shfl_xor_sync(0xffffffff, mx1, 2));
            float sc0 = exp2f(m_[mf][0] - mx0);
            float sc1 = exp2f(m_[mf][1] - mx1);
            m_[mf][0] = mx0; m_[mf][1] = mx1;
            float sum0 = 0.0f, sum1 = 0.0f;
#pragma unroll
            for (int nf = 0; nf < 8; nf++) {
                s_acc[mf][nf][0] = exp2f(s_acc[mf][nf][0] - mx0);
                s_acc[mf][nf][1] = exp2f(s_acc[mf][nf][1] - mx0);
                s_acc[mf][nf][2] = exp2f(s_acc[mf][nf][2] - mx1);
                s_acc[mf][nf][3] = exp2f(s_acc[mf][nf][3] - mx1);
                sum0 += s_acc[mf][nf][0] + s_acc[mf][nf][1];
                sum1 += s_acc[mf][nf][2] + s_acc[mf][nf][3];
            }
            sum0 += __shfl_xor_sync(0xffffffff, sum0, 1);
            sum0 += __shfl_xor_sync(0xffffffff, sum0, 2);
            sum1 += __shfl_xor_sync(0xffffffff, sum1, 1);
            sum1 += __shfl_xor_sync(0xffffffff, sum1, 2);
            l_[mf][0] = l_[mf][0] * sc0 + sum0;
            l_[mf][1] = l_[mf][1] * sc1 + sum1;
#pragma unroll
            for (int nf = 0; nf < 8; nf++) {
                o_acc[mf][nf][0] *= sc0; o_acc[mf][nf][1] *= sc0;
                o_acc[mf][nf][2] *= sc1; o_acc[mf][nf][3] *= sc1;
            }
        }

#pragma unroll
        for (int s = 0; s < 4; s++) {
            uint32_t pa[2][4];
#pragma unroll
            for (int mf = 0; mf < 2; mf++) {
                pa[mf][0] = pack_h2(s_acc[mf][2 * s][0],     s_acc[mf][2 * s][1]);
                pa[mf][1] = pack_h2(s_acc[mf][2 * s][2],     s_acc[mf][2 * s][3]);
                pa[mf][2] = pack_h2(s_acc[mf][2 * s + 1][0], s_acc[mf][2 * s + 1][1]);
                pa[mf][3] = pack_h2(s_acc[mf][2 * s + 1][2], s_acc[mf][2 * s + 1][3]);
            }
#pragma unroll
            for (int nf = 0; nf < 8; nf++) {
                const uint32_t* vp = (const uint32_t*)(st + 128 * ROWB + (nf * 8 + g) * ROWB) + s * 8 + tig;
                uint32_t b0 = vp[0], b1 = vp[4];
#pragma unroll
                for (int mf = 0; mf < 2; mf++)
                    mma_f16(o_acc[mf][nf], pa[mf][0], pa[mf][1], pa[mf][2], pa[mf][3], b0, b1);
            }
        }

        if (kb + 1 < NT) {
            char* nst = fsm + ST_OFF + ((kb + 1) & 1) * ST_SZ;
            uint4* khp = (uint4*)(nst + keyK * ROWB + d0K * 2);
            uint4* klp = (uint4*)(nst + 64 * ROWB + keyK * ROWB + d0K * 2);
#pragma unroll
            for (int j = 0; j < 4; j++) { khp[j] = kh[j]; klp[j] = kl[j]; }
            char* vt = nst + 128 * ROWB;
#pragma unroll
            for (int q = 0; q < 4; q++) {
                const __half* vh = (const __half*)&vv[q];
#pragma unroll
                for (int j = 0; j < 8; j++)
                    *(__half*)(vt + (d0V + 8 * q + j) * ROWB + keyV * 2) = vh[j];
            }
        }
        __syncthreads();
    }

    // ---- finalize: write O as single fp16 plane ----
#pragma unroll
    for (int mf = 0; mf < 2; mf++) {
        const int rA = wb + mf * 16 + g;
        const float inv0 = 1.0f / l_[mf][0];
        const float inv1 = 1.0f / l_[mf][1];
#pragma unroll
        for (int nf = 0; nf < 8; nf++) {
            const int col = col0 + nf * 8 + tig * 2;
            *(uint32_t*)(g_Oh + (qrow0 + rA) * D_MODEL + col) =
                pack_h2(o_acc[mf][nf][0] * inv0, o_acc[mf][nf][1] * inv0);
            *(uint32_t*)(g_Oh + (qrow0 + rA + 8) * D_MODEL + col) =
                pack_h2(o_acc[mf][nf][2] * inv1, o_acc[mf][nf][3] * inv1);
        }
    }
}

// ---------------- host launch ----------------
extern "C" void kernel_launch(void* const* d_in, const int* in_sizes, int n_in,
                              void* d_out, int out_size)
{
    const float* query = (const float*)d_in[0];
    const float* key   = (const float*)d_in[1];
    const float* value = (const float*)d_in[2];
    const float* w_q   = (const float*)d_in[3];
    const float* w_k   = (const float*)d_in[4];
    const float* w_v   = (const float*)d_in[5];
    const float* w_o   = (const float*)d_in[6];
    float* out = (float*)d_out;

    cudaFuncSetAttribute(flash_h5_kernel,
                         cudaFuncAttributeMaxDynamicSharedMemorySize, FLASH_SMEM);
    cudaFuncSetAttribute(gemm_h2_kernel,
                         cudaFuncAttributeMaxDynamicSharedMemorySize, GEMM_SMEM);

    zero_sums_kernel<<<1, 32>>>();
    abssum_kernel<<<dim3(128, 4), 256>>>(w_q, w_k, w_v, w_o);
    ternarize_kernel<<<dim3(D_MODEL * D_MODEL / 256, 4), 256>>>(w_q, w_k, w_v, w_o);

    presplit_kernel<<<dim3(PLN / 1024, 3), 256>>>(query, key, value);

    gemm_h2_kernel<<<dim3(D_MODEL / GBN, MROWS / GBM, 3), 256, GEMM_SMEM>>>(nullptr, 0);

    flash_h5_kernel<<<dim3(SEQ / FQT, NHEADS, BATCH), 128, FLASH_SMEM>>>();

    gemm_h2_kernel<<<dim3(D_MODEL / GBN, MROWS / GBM, 1), 256, GEMM_SMEM>>>(out, 1);
}